// round 5
// baseline (speedup 1.0000x reference)
#include <cuda_runtime.h>
#include <cuda_bf16.h>
#include <cstdint>

// ---------------------------------------------------------------------------
// MetaCNNLSTM: conv1d(64->256,k9,same) + GN(8)+ReLU -> 3x LSTM(512) -> mean -> head(50)
// B=32, T=512.
// Recurrent GEMM on mma.sync bf16 HMMA with COMPENSATED hi/lo split:
//   W@h ~= Whi@hhi + Whi@hlo + Wlo@hhi   (fp32 accum, error ~eps^2)
// 32 persistent blocks; per-step operands via cp.async.bulk + mbarrier.
// ---------------------------------------------------------------------------

#define B_      32
#define CIN     64
#define T_      512
#define NF      256
#define KW      9
#define GN_G    8
#define H_      512
#define G4H     2048
#define NCLS    50

#define NBLK    32
#define THR     256

// dynamic smem layout (byte offsets from 1024-aligned base)
#define SM_WHI   0          // A hi: 64 rows x 64 chunks(16B), chunk^=(row&7)    65536
#define SM_WLO   65536      // A lo                                              65536
#define SM_BHI   131072     // B hi: 32 rows x 64 chunks                         32768
#define SM_BLO   163840     // B lo (contiguous after BHI for single bulk copy)  32768
#define SM_GSM   196608     // gates [64][34] fp32                                8704
#define SM_XGS   205312     // xg staging [32][64] fp32                           8192
#define SM_HSMH  213504     // h hi staging [32][16] bf16                         1024
#define SM_HSML  214528     // h lo staging                                       1024
#define SM_MBAR  215552     // mbarrier (8B)
#define SM_TOTAL 215560
#define SMEM_REQ (SM_TOTAL + 1024)

// ---- global scratch ----
__device__ float g_conv[B_ * NF * T_];
__device__ float g_mu[B_ * GN_G];
__device__ float g_rs[B_ * GN_G];
__device__ float g_bufA[B_ * T_ * H_];
__device__ float g_bufB[B_ * T_ * H_];
__device__ float g_xg[T_ * NBLK * B_ * 64];            // [t][blk][b][g*16+cl]
// h images: [0,32KB) = hi, [32KB,64KB) = lo; row b = 1024B, chunk k16^(b&7)
__device__ __align__(1024) __nv_bfloat16 g_hbf2[2 * B_ * H_];
__device__ unsigned g_bar_count;
__device__ unsigned g_gen;

// ---------------------------------------------------------------------------
// helpers
// ---------------------------------------------------------------------------
__device__ __forceinline__ float2 ffma2(float2 a, float2 b, float2 c) {
    float2 d;
    asm("fma.rn.f32x2 %0, %1, %2, %3;"
        : "=l"(*(unsigned long long*)&d)
        : "l"(*(unsigned long long*)&a),
          "l"(*(unsigned long long*)&b),
          "l"(*(unsigned long long*)&c));
    return d;
}
__device__ __forceinline__ float sigmoidf(float x) { return 1.0f / (1.0f + __expf(-x)); }
__device__ __forceinline__ float tanh_fast(float x) { return 1.0f - 2.0f / (1.0f + __expf(2.0f * x)); }

__device__ __forceinline__ unsigned ld_acquire(unsigned* p) {
    unsigned v;
    asm volatile("ld.acquire.gpu.global.u32 %0, [%1];" : "=r"(v) : "l"(p) : "memory");
    return v;
}
__device__ __forceinline__ void st_release(unsigned* p, unsigned v) {
    asm volatile("st.release.gpu.global.u32 [%0], %1;" :: "l"(p), "r"(v) : "memory");
}
__device__ __forceinline__ uint32_t smem_u32(const void* p) {
    uint32_t a;
    asm("{ .reg .u64 t; cvta.to.shared.u64 t, %1; cvt.u32.u64 %0, t; }" : "=r"(a) : "l"(p));
    return a;
}
__device__ __forceinline__ uint32_t pack_bf16x2(float lo, float hi) {
    uint32_t r;
    asm("cvt.rn.bf16x2.f32 %0, %1, %2;" : "=r"(r) : "f"(hi), "f"(lo));
    return r;
}
// split a pair of floats into hi (bf16x2) and lo (bf16x2) packs
__device__ __forceinline__ uint32_t split_pair(float a, float b, uint32_t& lo_out) {
    __nv_bfloat16 ah = __float2bfloat16(a), bh = __float2bfloat16(b);
    float al = a - __bfloat162float(ah);
    float bl = b - __bfloat162float(bh);
    lo_out = pack_bf16x2(al, bl);
    return ((uint32_t)__bfloat16_as_ushort(bh) << 16) | (uint32_t)__bfloat16_as_ushort(ah);
}
__device__ __forceinline__ void sts128(uint32_t addr, uint4 v) {
    asm volatile("st.shared.v4.b32 [%0], {%1,%2,%3,%4};"
                 :: "r"(addr), "r"(v.x), "r"(v.y), "r"(v.z), "r"(v.w) : "memory");
}
__device__ __forceinline__ void ldmatrix4(uint32_t& r0, uint32_t& r1, uint32_t& r2, uint32_t& r3, uint32_t addr) {
    asm volatile("ldmatrix.sync.aligned.m8n8.x4.shared.b16 {%0,%1,%2,%3}, [%4];"
                 : "=r"(r0), "=r"(r1), "=r"(r2), "=r"(r3) : "r"(addr));
}
__device__ __forceinline__ void mma16816(float* c, uint32_t a0, uint32_t a1, uint32_t a2, uint32_t a3,
                                         uint32_t b0, uint32_t b1) {
    asm volatile("mma.sync.aligned.m16n8k16.row.col.f32.bf16.bf16.f32 "
                 "{%0,%1,%2,%3}, {%4,%5,%6,%7}, {%8,%9}, {%0,%1,%2,%3};"
                 : "+f"(c[0]), "+f"(c[1]), "+f"(c[2]), "+f"(c[3])
                 : "r"(a0), "r"(a1), "r"(a2), "r"(a3), "r"(b0), "r"(b1));
}

#define MBAR_WAIT(mbar, ph) do {                                                   \
    uint32_t _done;                                                                \
    asm volatile("{\n\t.reg .pred p;\n\t"                                          \
        "mbarrier.try_wait.parity.acquire.cta.shared::cta.b64 p, [%1], %2;\n\t"    \
        "selp.b32 %0, 1, 0, p;\n\t}"                                               \
        : "=r"(_done) : "r"(mbar), "r"(ph) : "memory");                            \
    if (!_done) {                                                                  \
        asm volatile("{\n\t.reg .pred P1;\n\t"                                     \
            "WL_%=:\n\t"                                                           \
            "mbarrier.try_wait.parity.acquire.cta.shared::cta.b64 P1, [%0], %1, 0x989680;\n\t" \
            "@P1 bra.uni WD_%=;\n\t"                                               \
            "bra.uni WL_%=;\n\t"                                                   \
            "WD_%=:\n\t}"                                                          \
            :: "r"(mbar), "r"(ph) : "memory");                                     \
    }                                                                              \
} while (0)

// ---------------------------------------------------------------------------
__global__ void dummy_kernel() {}

// ---------------------------------------------------------------------------
// conv1d / groupnorm
// ---------------------------------------------------------------------------
__global__ void conv_kernel(const float* __restrict__ x, const float* __restrict__ w) {
    int bf = blockIdx.x;
    int b = bf >> 8, f = bf & 255;
    __shared__ float wsh[CIN * KW];
    for (int e = threadIdx.x; e < CIN * KW; e += blockDim.x)
        wsh[e] = w[f * CIN * KW + e];
    __syncthreads();
    const float* xb = x + b * CIN * T_;
    #pragma unroll
    for (int tt = 0; tt < 4; ++tt) {
        int t = tt * 128 + threadIdx.x;
        float acc = 0.f;
        for (int c = 0; c < CIN; ++c) {
            const float* xr = xb + c * T_;
            const float* wr = wsh + c * KW;
            #pragma unroll
            for (int k = 0; k < KW; ++k) {
                int ti = t + k - 4;
                if (ti >= 0 && ti < T_) acc += xr[ti] * wr[k];
            }
        }
        g_conv[(b * NF + f) * T_ + t] = acc;
    }
}

__global__ void gn_stats_kernel() {
    int bg = blockIdx.x;
    int b = bg >> 3, g = bg & 7;
    const int CPG = NF / GN_G;
    const float* base = g_conv + (b * NF + g * CPG) * T_;
    float s = 0.f, ss = 0.f;
    for (int e = threadIdx.x; e < CPG * T_; e += blockDim.x) {
        float v = base[e];
        s += v; ss += v * v;
    }
    __shared__ float sh_s[256], sh_q[256];
    sh_s[threadIdx.x] = s; sh_q[threadIdx.x] = ss;
    __syncthreads();
    for (int st = 128; st > 0; st >>= 1) {
        if (threadIdx.x < st) {
            sh_s[threadIdx.x] += sh_s[threadIdx.x + st];
            sh_q[threadIdx.x] += sh_q[threadIdx.x + st];
        }
        __syncthreads();
    }
    if (threadIdx.x == 0) {
        float n = (float)(CPG * T_);
        float mu = sh_s[0] / n;
        float var = sh_q[0] / n - mu * mu;
        g_mu[bg] = mu;
        g_rs[bg] = rsqrtf(var + 1e-5f);
    }
}

__global__ void gn_apply_kernel(const float* __restrict__ gamma, const float* __restrict__ beta) {
    int idx = blockIdx.x * blockDim.x + threadIdx.x;
    if (idx >= B_ * NF * T_) return;
    int t = idx & 511;
    int f = (idx >> 9) & 255;
    int b = idx >> 17;
    int g = f >> 5;
    float v = g_conv[idx];
    v = (v - g_mu[b * 8 + g]) * g_rs[b * 8 + g] * gamma[f] + beta[f];
    v = fmaxf(v, 0.f);
    g_bufA[(b * T_ + t) * NF + f] = v;
}

// ---------------------------------------------------------------------------
// input-projection SGEMM; epilogue writes block-contiguous xg layout:
//   g_xg[((t*32 + blk)*32 + b)*64 + g*16 + cl],  blk=cell/16, cl=cell%16
// ---------------------------------------------------------------------------
__global__ __launch_bounds__(256) void xg_gemm_kernel(int layer,
                                                      const float* __restrict__ Wih,
                                                      const float* __restrict__ bias,
                                                      int Din) {
    const float* X = (layer == 2) ? g_bufB : g_bufA;
    __shared__ __align__(16) float As[8][128];
    __shared__ __align__(16) float Bs[8][128];

    int m0 = blockIdx.y * 128, n0 = blockIdx.x * 128;
    int tid = threadIdx.x;
    int tx = tid & 15, ty = tid >> 4;
    int lrow = tid >> 1;
    int lcol = (tid & 1) * 4;

    int m = m0 + lrow;
    int ab = m & 31, at = m >> 5;
    const float* arow_p = X + (size_t)(ab * T_ + at) * Din;
    const float* brow_p = Wih + (size_t)(n0 + lrow) * Din;

    float2 acc[8][4];
    #pragma unroll
    for (int i = 0; i < 8; ++i)
        #pragma unroll
        for (int j = 0; j < 4; ++j) acc[i][j] = make_float2(0.f, 0.f);

    for (int k0 = 0; k0 < Din; k0 += 8) {
        float4 av = *(const float4*)(arow_p + k0 + lcol);
        float4 bv = *(const float4*)(brow_p + k0 + lcol);
        As[lcol + 0][lrow] = av.x; As[lcol + 1][lrow] = av.y;
        As[lcol + 2][lrow] = av.z; As[lcol + 3][lrow] = av.w;
        Bs[lcol + 0][lrow] = bv.x; Bs[lcol + 1][lrow] = bv.y;
        Bs[lcol + 2][lrow] = bv.z; Bs[lcol + 3][lrow] = bv.w;
        __syncthreads();
        #pragma unroll
        for (int kk = 0; kk < 8; ++kk) {
            float a[8];
            #pragma unroll
            for (int vm = 0; vm < 8; ++vm) a[vm] = As[kk][ty * 8 + vm];
            float2 w2[4];
            #pragma unroll
            for (int u = 0; u < 4; ++u)
                w2[u] = *(const float2*)&Bs[kk][tx * 2 + 32 * u];
            #pragma unroll
            for (int vm = 0; vm < 8; ++vm) {
                float2 a2 = make_float2(a[vm], a[vm]);
                #pragma unroll
                for (int u = 0; u < 4; ++u)
                    acc[vm][u] = ffma2(a2, w2[u], acc[vm][u]);
            }
        }
        __syncthreads();
    }

    #pragma unroll
    for (int vm = 0; vm < 8; ++vm) {
        int mm = m0 + ty * 8 + vm;
        int t = mm >> 5, b = mm & 31;
        #pragma unroll
        for (int u = 0; u < 4; ++u) {
            int n = n0 + tx * 2 + 32 * u;
            int g = n >> 9, cell = n & 511;
            int blk = cell >> 4, cl = cell & 15;
            float2 r = acc[vm][u];
            r.x += bias[n]; r.y += bias[n + 1];
            *(float2*)&g_xg[(((size_t)t * 32 + blk) * 32 + b) * 64 + g * 16 + cl] = r;
        }
    }
}

// ---------------------------------------------------------------------------
// persistent HMMA LSTM (compensated bf16): 32 blocks, block bx owns cells
// [bx*16, bx*16+16). A row r <-> (gate=r&3, cell=bx*16+(r>>2)). B row = batch.
// ---------------------------------------------------------------------------
__global__ __launch_bounds__(THR, 1) void lstm_kernel(const float* __restrict__ Whh,
                                                      const float* __restrict__ xg,
                                                      float* __restrict__ Y) {
    extern __shared__ char smraw[];
    uint32_t rawa = smem_u32(smraw);
    uint32_t base = (rawa + 1023u) & ~1023u;
    char* sbase = smraw + (base - rawa);
    uint32_t wHI  = base + SM_WHI;
    uint32_t wLO  = base + SM_WLO;
    uint32_t bHI  = base + SM_BHI;
    uint32_t bLO  = base + SM_BLO;
    float*   gsm  = (float*)(sbase + SM_GSM);
    float*   xgs  = (float*)(sbase + SM_XGS);
    __nv_bfloat16* hsmh = (__nv_bfloat16*)(sbase + SM_HSMH);
    __nv_bfloat16* hsml = (__nv_bfloat16*)(sbase + SM_HSML);
    uint32_t mbar = base + SM_MBAR;
    uint32_t xgs_a = base + SM_XGS;

    const int tid = threadIdx.x;
    const int bx = blockIdx.x;
    const int c0 = bx * 16;
    const int wid = tid >> 5, lane = tid & 31;

    unsigned mygen = *((volatile unsigned*)&g_gen);

    if (tid == 0) {
        asm volatile("mbarrier.init.shared.b64 [%0], %1;" :: "r"(mbar), "r"(1u) : "memory");
    }

    // --- stage W tile: 64 rows x 64 chunks, fp32 -> bf16 hi/lo, chunk^=(row&7) ---
    #pragma unroll
    for (int i = 0; i < 16; ++i) {
        int g = tid + i * 256;            // 4096 chunks
        int r = g >> 6, k16 = g & 63;
        int j = (r & 3) * 512 + c0 + (r >> 2);
        const float* src = Whh + (size_t)j * 512 + k16 * 8;
        float4 f0 = *(const float4*)(src);
        float4 f1 = *(const float4*)(src + 4);
        uint4 vh, vl;
        vh.x = split_pair(f0.x, f0.y, vl.x);
        vh.y = split_pair(f0.z, f0.w, vl.y);
        vh.z = split_pair(f1.x, f1.y, vl.z);
        vh.w = split_pair(f1.z, f1.w, vl.w);
        uint32_t off = (uint32_t)((r << 10) + (((k16 ^ (r & 7))) << 4));
        sts128(wHI + off, vh);
        sts128(wLO + off, vl);
    }

    // --- zero this block's chunks of g_hbf2 (hi at tid<64, lo at tid>=64) ---
    if (tid < 128) {
        int tt = tid & 63;
        int b = tt >> 1, q = tt & 1;
        uint32_t off = (uint32_t)((b << 10) + (((bx * 2 + q) ^ (b & 7)) << 4)) + (tid >= 64 ? 32768u : 0u);
        *(uint4*)((char*)g_hbf2 + off) = make_uint4(0, 0, 0, 0);
    }

    __syncthreads();
    if (tid == 0) {
        __threadfence();
        unsigned a = atomicAdd(&g_bar_count, 1u);
        if (a == NBLK - 1u) { g_bar_count = 0u; st_release(&g_gen, mygen + 1u); }
        else { while (ld_acquire(&g_gen) == mygen) {} }
    }
    mygen++;
    __syncthreads();

    // GEMM thread mapping
    const int wm = wid & 3, wn = wid >> 2;
    const int lrow = lane & 15, lk = lane >> 4;
    const uint32_t rowoff = (uint32_t)(((wm * 16 + lrow) << 10));
    const uint32_t browoff = (uint32_t)(((wn * 16 + lrow) << 10));
    const int x7 = lrow & 7;

    // activation mapping: cl = tid>>4, batches bb, bb+1 with bb = (tid&15)*2
    const int cl = tid >> 4;
    const int bb = (tid & 15) * 2;
    float cst0 = 0.f, cst1 = 0.f;

    const char* xg_src = (const char*)(xg + (size_t)bx * 2048);

    for (int t = 0; t < T_; ++t) {
        // 1. bulk copies: h hi+lo (64KB, one copy) + xg slice (8KB)
        if (tid == 0) {
            asm volatile("mbarrier.arrive.expect_tx.shared.b64 _, [%0], %1;"
                         :: "r"(mbar), "r"(73728u) : "memory");
            asm volatile("cp.async.bulk.shared::cluster.global.mbarrier::complete_tx::bytes "
                         "[%0], [%1], %2, [%3];"
                         :: "r"(bHI), "l"((const char*)g_hbf2), "r"(65536u), "r"(mbar) : "memory");
            asm volatile("cp.async.bulk.shared::cluster.global.mbarrier::complete_tx::bytes "
                         "[%0], [%1], %2, [%3];"
                         :: "r"(xgs_a), "l"(xg_src + (size_t)t * (NBLK * B_ * 64 * 4)), "r"(8192u), "r"(mbar) : "memory");
        }
        MBAR_WAIT(mbar, (uint32_t)(t & 1));

        // 2. GEMM: 32 k-steps, compensated: aHi*bHi + aHi*bLo + aLo*bHi
        float acc0[4] = {0.f, 0.f, 0.f, 0.f};
        float acc1[4] = {0.f, 0.f, 0.f, 0.f};
        #pragma unroll 8
        for (int ks = 0; ks < 32; ++ks) {
            uint32_t off = (uint32_t)((((ks * 2 + lk) ^ x7)) << 4);
            uint32_t ah0, ah1, ah2, ah3, al0, al1, al2, al3;
            uint32_t bh0, bh1, bh2, bh3, bl0, bl1, bl2, bl3;
            ldmatrix4(ah0, ah1, ah2, ah3, wHI + rowoff + off);
            ldmatrix4(al0, al1, al2, al3, wLO + rowoff + off);
            ldmatrix4(bh0, bh1, bh2, bh3, bHI + browoff + off);
            ldmatrix4(bl0, bl1, bl2, bl3, bLO + browoff + off);
            mma16816(acc0, ah0, ah1, ah2, ah3, bh0, bh2);
            mma16816(acc1, ah0, ah1, ah2, ah3, bh1, bh3);
            mma16816(acc0, ah0, ah1, ah2, ah3, bl0, bl2);
            mma16816(acc1, ah0, ah1, ah2, ah3, bl1, bl3);
            mma16816(acc0, al0, al1, al2, al3, bh0, bh2);
            mma16816(acc1, al0, al1, al2, al3, bh1, bh3);
        }

        // 3. store gates to gsm
        {
            int r0 = wm * 16 + (lane >> 2);
            int cb = wn * 16 + (lane & 3) * 2;
            *(float2*)&gsm[r0 * 34 + cb]            = make_float2(acc0[0], acc0[1]);
            *(float2*)&gsm[(r0 + 8) * 34 + cb]      = make_float2(acc0[2], acc0[3]);
            *(float2*)&gsm[r0 * 34 + cb + 8]        = make_float2(acc1[0], acc1[1]);
            *(float2*)&gsm[(r0 + 8) * 34 + cb + 8]  = make_float2(acc1[2], acc1[3]);
        }
        __syncthreads();

        // 4. activations (2 batches per thread), c-state in regs
        {
            const float* gI = gsm + (cl * 4 + 0) * 34;
            const float* gF = gsm + (cl * 4 + 1) * 34;
            const float* gG = gsm + (cl * 4 + 2) * 34;
            const float* gO = gsm + (cl * 4 + 3) * 34;
            const float* x0 = xgs + bb * 64 + cl;
            const float* x1 = xgs + (bb + 1) * 64 + cl;

            float i0 = sigmoidf(gI[bb] + x0[0]);
            float f0 = sigmoidf(gF[bb] + x0[16]);
            float g0 = tanh_fast(gG[bb] + x0[32]);
            float o0 = sigmoidf(gO[bb] + x0[48]);
            cst0 = f0 * cst0 + i0 * g0;
            float h0 = o0 * tanh_fast(cst0);

            float i1 = sigmoidf(gI[bb + 1] + x1[0]);
            float f1 = sigmoidf(gF[bb + 1] + x1[16]);
            float g1 = tanh_fast(gG[bb + 1] + x1[32]);
            float o1 = sigmoidf(gO[bb + 1] + x1[48]);
            cst1 = f1 * cst1 + i1 * g1;
            float h1 = o1 * tanh_fast(cst1);

            __nv_bfloat16 h0h = __float2bfloat16(h0);
            __nv_bfloat16 h1h = __float2bfloat16(h1);
            hsmh[bb * 16 + cl] = h0h;
            hsmh[(bb + 1) * 16 + cl] = h1h;
            hsml[bb * 16 + cl] = __float2bfloat16(h0 - __bfloat162float(h0h));
            hsml[(bb + 1) * 16 + cl] = __float2bfloat16(h1 - __bfloat162float(h1h));
            Y[((size_t)bb * T_ + t) * H_ + c0 + cl] = h0;
            Y[((size_t)(bb + 1) * T_ + t) * H_ + c0 + cl] = h1;
        }
        __syncthreads();

        // 5. publish h hi/lo slices into swizzled g_hbf2
        if (tid < 128) {
            int tt = tid & 63;
            int b = tt >> 1, q = tt & 1;
            const __nv_bfloat16* s = (tid < 64) ? hsmh : hsml;
            uint4 v = *(const uint4*)(s + b * 16 + q * 8);
            uint32_t off = (uint32_t)((b << 10) + (((bx * 2 + q) ^ (b & 7)) << 4)) + (tid >= 64 ? 32768u : 0u);
            *(uint4*)((char*)g_hbf2 + off) = v;
        }

        // 6. grid barrier
        __syncthreads();
        if (tid == 0) {
            __threadfence();
            unsigned a = atomicAdd(&g_bar_count, 1u);
            if (a == NBLK - 1u) { g_bar_count = 0u; st_release(&g_gen, mygen + 1u); }
            else { while (ld_acquire(&g_gen) == mygen) {} }
        }
        mygen++;
        __syncthreads();
    }
}

// ---------------------------------------------------------------------------
// mean over T + head GEMV
// ---------------------------------------------------------------------------
__global__ void pool_head_kernel(const float* __restrict__ head_w,
                                 const float* __restrict__ head_b,
                                 float* __restrict__ out) {
    int b = blockIdx.x;
    int h = threadIdx.x;
    __shared__ float feat[H_];
    const float* Yp = g_bufB + (size_t)b * T_ * H_;
    float s = 0.f;
    for (int t = 0; t < T_; ++t) s += Yp[t * H_ + h];
    feat[h] = s * (1.0f / (float)T_);
    __syncthreads();
    for (int cc = threadIdx.x; cc < NCLS; cc += blockDim.x) {
        float a = head_b[cc];
        const float* wr = head_w + cc * H_;
        for (int k = 0; k < H_; ++k) a += feat[k] * wr[k];
        out[b * NCLS + cc] = a;
    }
}

// ---------------------------------------------------------------------------
extern "C" void kernel_launch(void* const* d_in, const int* in_sizes, int n_in,
                              void* d_out, int out_size) {
    const float* x     = (const float*)d_in[0];
    const float* convw = (const float*)d_in[1];
    const float* gamma = (const float*)d_in[2];
    const float* beta  = (const float*)d_in[3];

    bool head_first = (in_sizes[4] == NCLS * H_);
    int o = head_first ? 6 : 4;
    const float* headw = (const float*)d_in[head_first ? 4 : 13];
    const float* headb = (const float*)d_in[head_first ? 5 : 14];
    const float* wih[3] = { (const float*)d_in[o + 0], (const float*)d_in[o + 3], (const float*)d_in[o + 6] };
    const float* whh[3] = { (const float*)d_in[o + 1], (const float*)d_in[o + 4], (const float*)d_in[o + 7] };
    const float* bb[3]  = { (const float*)d_in[o + 2], (const float*)d_in[o + 5], (const float*)d_in[o + 8] };

    static int smem_set = 0;
    if (!smem_set) {
        cudaFuncSetAttribute(lstm_kernel, cudaFuncAttributeMaxDynamicSharedMemorySize, SMEM_REQ);
        smem_set = 1;
    }

    void* xgsym = nullptr;   cudaGetSymbolAddress(&xgsym, g_xg);
    void* bufAsym = nullptr; cudaGetSymbolAddress(&bufAsym, g_bufA);
    void* bufBsym = nullptr; cudaGetSymbolAddress(&bufBsym, g_bufB);

    dummy_kernel<<<1, 32>>>();                       // 0
    conv_kernel<<<B_ * NF, 128>>>(x, convw);         // 1
    gn_stats_kernel<<<B_ * GN_G, 256>>>();           // 2
    gn_apply_kernel<<<(B_ * NF * T_ + 255) / 256, 256>>>(gamma, beta);  // 3

    for (int layer = 1; layer <= 3; ++layer) {
        int din = (layer == 1) ? NF : H_;
        dim3 gg(G4H / 128, (B_ * T_) / 128);
        xg_gemm_kernel<<<gg, 256>>>(layer, wih[layer - 1], bb[layer - 1], din);   // 4,6,8
        float* yptr = (layer == 2) ? (float*)bufAsym : (float*)bufBsym;
        lstm_kernel<<<NBLK, THR, SMEM_REQ>>>(whh[layer - 1], (const float*)xgsym, yptr);  // 5,7,9
    }

    pool_head_kernel<<<B_, H_>>>(headw, headb, (float*)d_out);
}

// round 6
// speedup vs baseline: 1.1117x; 1.1117x over previous
#include <cuda_runtime.h>
#include <cuda_bf16.h>
#include <cuda_fp16.h>
#include <cstdint>

// ---------------------------------------------------------------------------
// MetaCNNLSTM: conv1d(64->256,k9,same) + GN(8)+ReLU -> 3x LSTM(512) -> mean -> head(50)
// B=32, T=512.
// Recurrent GEMM: mma.sync fp16 HMMA, compensated hi/lo (3 passes, err~eps^2),
// 64 persistent blocks (M=32 rows each), 3 independent accumulator chains,
// bulk-copied operands + double-buffered xg prefetch, 1 grid barrier/step.
// ---------------------------------------------------------------------------

#define B_      32
#define CIN     64
#define T_      512
#define NF      256
#define KW      9
#define GN_G    8
#define H_      512
#define G4H     2048
#define NCLS    50

#define NBLK    64
#define THR     256

// dynamic smem layout (byte offsets from 1024-aligned base)
#define SM_WHI   0          // A hi: 32 rows x 64 chunks(16B) fp16, chunk^=(row&7)  32768
#define SM_WLO   32768      // A lo                                                 32768
#define SM_BHI   65536      // B(h) hi: 32 rows x 64 chunks                         32768
#define SM_BLO   98304      // B(h) lo (contiguous: one bulk copy)                  32768
#define SM_GSM   131072     // gates [32][34] fp32                                   4352
#define SM_XGS   135424     // xg staging 2 x [32][32] fp32                          8192
#define SM_HSMH  143616     // h hi staging [32][8] fp16                              512
#define SM_HSML  144128     // h lo staging                                           512
#define SM_MBAR  144640     // mbarrier (8B)
#define SM_TOTAL 144648
#define SMEM_REQ (SM_TOTAL + 1024)

// ---- global scratch ----
__device__ float g_conv[B_ * NF * T_];
__device__ float g_bufA[B_ * T_ * H_];
__device__ float g_bufB[B_ * T_ * H_];
__device__ __align__(4096) float g_xg[T_ * NBLK * B_ * 32];   // [t][blk][b][g*8+cl]
// h images: [0,32KB) hi, [32KB,64KB) lo; row b = 1024B (512 fp16), chunk k16^(b&7)
__device__ __align__(1024) __half g_h2[2 * B_ * H_];
__device__ unsigned g_bar_count;
__device__ unsigned g_gen;

// ---------------------------------------------------------------------------
// helpers
// ---------------------------------------------------------------------------
__device__ __forceinline__ float2 ffma2(float2 a, float2 b, float2 c) {
    float2 d;
    asm("fma.rn.f32x2 %0, %1, %2, %3;"
        : "=l"(*(unsigned long long*)&d)
        : "l"(*(unsigned long long*)&a),
          "l"(*(unsigned long long*)&b),
          "l"(*(unsigned long long*)&c));
    return d;
}
__device__ __forceinline__ float sigmoidf(float x) { return 1.0f / (1.0f + __expf(-x)); }
__device__ __forceinline__ float tanh_fast(float x) { return 1.0f - 2.0f / (1.0f + __expf(2.0f * x)); }

__device__ __forceinline__ unsigned ld_acquire(unsigned* p) {
    unsigned v;
    asm volatile("ld.acquire.gpu.global.u32 %0, [%1];" : "=r"(v) : "l"(p) : "memory");
    return v;
}
__device__ __forceinline__ void st_release(unsigned* p, unsigned v) {
    asm volatile("st.release.gpu.global.u32 [%0], %1;" :: "l"(p), "r"(v) : "memory");
}
__device__ __forceinline__ uint32_t smem_u32(const void* p) {
    uint32_t a;
    asm("{ .reg .u64 t; cvta.to.shared.u64 t, %1; cvt.u32.u64 %0, t; }" : "=r"(a) : "l"(p));
    return a;
}
// split pair of floats into fp16 hi pack and fp16 lo (residual) pack
__device__ __forceinline__ uint32_t split_pair_h(float a, float b, uint32_t& lo_out) {
    __half ha = __float2half_rn(a), hb = __float2half_rn(b);
    float la = a - __half2float(ha);
    float lb = b - __half2float(hb);
    __half2 lo2 = __halves2half2(__float2half_rn(la), __float2half_rn(lb));
    __half2 hi2 = __halves2half2(ha, hb);
    lo_out = *reinterpret_cast<uint32_t*>(&lo2);
    return *reinterpret_cast<uint32_t*>(&hi2);
}
__device__ __forceinline__ void sts128(uint32_t addr, uint4 v) {
    asm volatile("st.shared.v4.b32 [%0], {%1,%2,%3,%4};"
                 :: "r"(addr), "r"(v.x), "r"(v.y), "r"(v.z), "r"(v.w) : "memory");
}
__device__ __forceinline__ void ldmatrix4(uint32_t& r0, uint32_t& r1, uint32_t& r2, uint32_t& r3, uint32_t addr) {
    asm volatile("ldmatrix.sync.aligned.m8n8.x4.shared.b16 {%0,%1,%2,%3}, [%4];"
                 : "=r"(r0), "=r"(r1), "=r"(r2), "=r"(r3) : "r"(addr));
}
__device__ __forceinline__ void ldmatrix2(uint32_t& r0, uint32_t& r1, uint32_t addr) {
    asm volatile("ldmatrix.sync.aligned.m8n8.x2.shared.b16 {%0,%1}, [%2];"
                 : "=r"(r0), "=r"(r1) : "r"(addr));
}
__device__ __forceinline__ void mma16816h(float* c, uint32_t a0, uint32_t a1, uint32_t a2, uint32_t a3,
                                          uint32_t b0, uint32_t b1) {
    asm volatile("mma.sync.aligned.m16n8k16.row.col.f32.f16.f16.f32 "
                 "{%0,%1,%2,%3}, {%4,%5,%6,%7}, {%8,%9}, {%0,%1,%2,%3};"
                 : "+f"(c[0]), "+f"(c[1]), "+f"(c[2]), "+f"(c[3])
                 : "r"(a0), "r"(a1), "r"(a2), "r"(a3), "r"(b0), "r"(b1));
}

#define MBAR_WAIT(mbar, ph) do {                                                   \
    uint32_t _done;                                                                \
    asm volatile("{\n\t.reg .pred p;\n\t"                                          \
        "mbarrier.try_wait.parity.acquire.cta.shared::cta.b64 p, [%1], %2;\n\t"    \
        "selp.b32 %0, 1, 0, p;\n\t}"                                               \
        : "=r"(_done) : "r"(mbar), "r"(ph) : "memory");                            \
    if (!_done) {                                                                  \
        asm volatile("{\n\t.reg .pred P1;\n\t"                                     \
            "WL_%=:\n\t"                                                           \
            "mbarrier.try_wait.parity.acquire.cta.shared::cta.b64 P1, [%0], %1, 0x989680;\n\t" \
            "@P1 bra.uni WD_%=;\n\t"                                               \
            "bra.uni WL_%=;\n\t"                                                   \
            "WD_%=:\n\t}"                                                          \
            :: "r"(mbar), "r"(ph) : "memory");                                     \
    }                                                                              \
} while (0)

// ---------------------------------------------------------------------------
// conv1d
// ---------------------------------------------------------------------------
__global__ void conv_kernel(const float* __restrict__ x, const float* __restrict__ w) {
    int bf = blockIdx.x;
    int b = bf >> 8, f = bf & 255;
    __shared__ float wsh[CIN * KW];
    for (int e = threadIdx.x; e < CIN * KW; e += blockDim.x)
        wsh[e] = w[f * CIN * KW + e];
    __syncthreads();
    const float* xb = x + b * CIN * T_;
    #pragma unroll
    for (int tt = 0; tt < 4; ++tt) {
        int t = tt * 128 + threadIdx.x;
        float acc = 0.f;
        for (int c = 0; c < CIN; ++c) {
            const float* xr = xb + c * T_;
            const float* wr = wsh + c * KW;
            #pragma unroll
            for (int k = 0; k < KW; ++k) {
                int ti = t + k - 4;
                if (ti >= 0 && ti < T_) acc += xr[ti] * wr[k];
            }
        }
        g_conv[(b * NF + f) * T_ + t] = acc;
    }
}

// ---------------------------------------------------------------------------
// fused GroupNorm (stats + apply + ReLU + transpose -> g_bufA)
// ---------------------------------------------------------------------------
__global__ void gn_kernel(const float* __restrict__ gamma, const float* __restrict__ beta) {
    int bg = blockIdx.x;              // 256 blocks: (b, g)
    int b = bg >> 3, g = bg & 7;
    const float* base = g_conv + (b * NF + g * 32) * T_;
    float s = 0.f, ss = 0.f;
    for (int e = threadIdx.x; e < 32 * T_; e += blockDim.x) {
        float v = base[e];
        s += v; ss += v * v;
    }
    __shared__ float sh_s[256], sh_q[256];
    sh_s[threadIdx.x] = s; sh_q[threadIdx.x] = ss;
    __syncthreads();
    for (int st = 128; st > 0; st >>= 1) {
        if (threadIdx.x < st) {
            sh_s[threadIdx.x] += sh_s[threadIdx.x + st];
            sh_q[threadIdx.x] += sh_q[threadIdx.x + st];
        }
        __syncthreads();
    }
    __shared__ float sh_mu, sh_rs;
    if (threadIdx.x == 0) {
        float n = 32.0f * (float)T_;
        float mu = sh_s[0] / n;
        float var = sh_q[0] / n - mu * mu;
        sh_mu = mu;
        sh_rs = rsqrtf(var + 1e-5f);
    }
    __syncthreads();
    float mu = sh_mu, rs = sh_rs;
    for (int e = threadIdx.x; e < 32 * T_; e += blockDim.x) {
        int cl = e >> 9, t = e & 511;
        int f = g * 32 + cl;
        float v = (base[e] - mu) * rs * gamma[f] + beta[f];
        v = fmaxf(v, 0.f);
        g_bufA[(b * T_ + t) * NF + f] = v;
    }
}

// ---------------------------------------------------------------------------
// input-projection SGEMM; epilogue writes block-contiguous xg layout:
//   g_xg[((t*64 + blk)*32 + b)*32 + g*8 + cl],  blk=cell/8, cl=cell%8
// ---------------------------------------------------------------------------
__global__ __launch_bounds__(256) void xg_gemm_kernel(int layer,
                                                      const float* __restrict__ Wih,
                                                      const float* __restrict__ bias,
                                                      int Din) {
    const float* X = (layer == 2) ? g_bufB : g_bufA;
    __shared__ __align__(16) float As[8][128];
    __shared__ __align__(16) float Bs[8][128];

    int m0 = blockIdx.y * 128, n0 = blockIdx.x * 128;
    int tid = threadIdx.x;
    int tx = tid & 15, ty = tid >> 4;
    int lrow = tid >> 1;
    int lcol = (tid & 1) * 4;

    int m = m0 + lrow;
    int ab = m & 31, at = m >> 5;
    const float* arow_p = X + (size_t)(ab * T_ + at) * Din;
    const float* brow_p = Wih + (size_t)(n0 + lrow) * Din;

    float2 acc[8][4];
    #pragma unroll
    for (int i = 0; i < 8; ++i)
        #pragma unroll
        for (int j = 0; j < 4; ++j) acc[i][j] = make_float2(0.f, 0.f);

    for (int k0 = 0; k0 < Din; k0 += 8) {
        float4 av = *(const float4*)(arow_p + k0 + lcol);
        float4 bv = *(const float4*)(brow_p + k0 + lcol);
        As[lcol + 0][lrow] = av.x; As[lcol + 1][lrow] = av.y;
        As[lcol + 2][lrow] = av.z; As[lcol + 3][lrow] = av.w;
        Bs[lcol + 0][lrow] = bv.x; Bs[lcol + 1][lrow] = bv.y;
        Bs[lcol + 2][lrow] = bv.z; Bs[lcol + 3][lrow] = bv.w;
        __syncthreads();
        #pragma unroll
        for (int kk = 0; kk < 8; ++kk) {
            float a[8];
            #pragma unroll
            for (int vm = 0; vm < 8; ++vm) a[vm] = As[kk][ty * 8 + vm];
            float2 w2[4];
            #pragma unroll
            for (int u = 0; u < 4; ++u)
                w2[u] = *(const float2*)&Bs[kk][tx * 2 + 32 * u];
            #pragma unroll
            for (int vm = 0; vm < 8; ++vm) {
                float2 a2 = make_float2(a[vm], a[vm]);
                #pragma unroll
                for (int u = 0; u < 4; ++u)
                    acc[vm][u] = ffma2(a2, w2[u], acc[vm][u]);
            }
        }
        __syncthreads();
    }

    #pragma unroll
    for (int vm = 0; vm < 8; ++vm) {
        int mm = m0 + ty * 8 + vm;
        int t = mm >> 5, b = mm & 31;
        #pragma unroll
        for (int u = 0; u < 4; ++u) {
            int n = n0 + tx * 2 + 32 * u;
            int g = n >> 9, cell = n & 511;
            int blk = cell >> 3, cl = cell & 7;
            float2 r = acc[vm][u];
            r.x += bias[n]; r.y += bias[n + 1];
            *(float2*)&g_xg[(((size_t)t * NBLK + blk) * 32 + b) * 32 + g * 8 + cl] = r;
        }
    }
}

// ---------------------------------------------------------------------------
// persistent HMMA LSTM (compensated fp16): 64 blocks, block bx owns cells
// [bx*8, bx*8+8). A row r <-> (gate=r&3, cell=bx*8+(r>>2)). B row = batch.
// warps: wm = wid&1 (m16 half), wn = wid>>1 (n8 group).
// ---------------------------------------------------------------------------
__global__ __launch_bounds__(THR, 1) void lstm_kernel(const float* __restrict__ Whh,
                                                      const float* __restrict__ xg,
                                                      float* __restrict__ Y) {
    extern __shared__ char smraw[];
    uint32_t rawa = smem_u32(smraw);
    uint32_t base = (rawa + 1023u) & ~1023u;
    char* sbase = smraw + (base - rawa);
    uint32_t wHI  = base + SM_WHI;
    uint32_t wLO  = base + SM_WLO;
    uint32_t bHI  = base + SM_BHI;
    uint32_t bLO  = base + SM_BLO;
    float*   gsm  = (float*)(sbase + SM_GSM);
    float*   xgs  = (float*)(sbase + SM_XGS);
    __half*  hsmh = (__half*)(sbase + SM_HSMH);
    __half*  hsml = (__half*)(sbase + SM_HSML);
    uint32_t mbar = base + SM_MBAR;
    uint32_t xgs_a = base + SM_XGS;

    const int tid = threadIdx.x;
    const int bx = blockIdx.x;
    const int wid = tid >> 5, lane = tid & 31;

    unsigned mygen = *((volatile unsigned*)&g_gen);

    if (tid == 0) {
        asm volatile("mbarrier.init.shared.b64 [%0], %1;" :: "r"(mbar), "r"(1u) : "memory");
    }

    // --- stage W tile: 32 rows x 64 chunks(16B), fp32 -> fp16 hi/lo, chunk^=(row&7) ---
    #pragma unroll
    for (int i = 0; i < 8; ++i) {
        int g = tid + i * 256;            // 2048 chunks
        int r = g >> 6, k16 = g & 63;
        int j = (r & 3) * 512 + bx * 8 + (r >> 2);
        const float* src = Whh + (size_t)j * 512 + k16 * 8;
        float4 f0 = *(const float4*)(src);
        float4 f1 = *(const float4*)(src + 4);
        uint4 vh, vl;
        vh.x = split_pair_h(f0.x, f0.y, vl.x);
        vh.y = split_pair_h(f0.z, f0.w, vl.y);
        vh.z = split_pair_h(f1.x, f1.y, vl.z);
        vh.w = split_pair_h(f1.z, f1.w, vl.w);
        uint32_t off = (uint32_t)((r << 10) + (((k16 ^ (r & 7))) << 4));
        sts128(wHI + off, vh);
        sts128(wLO + off, vl);
    }

    // --- zero this block's chunk (index bx) of both g_h2 images ---
    if (tid < 64) {
        int b = tid >> 1, img = tid & 1;
        uint32_t off = (uint32_t)(img * 32768 + (b << 10) + (((bx ^ (b & 7))) << 4));
        *(uint4*)((char*)g_h2 + off) = make_uint4(0, 0, 0, 0);
    }

    // --- prologue: prefetch xg(t=0) into buffer 0 ---
    __syncthreads();
    if (tid == 0) {
        asm volatile("mbarrier.arrive.expect_tx.shared.b64 _, [%0], %1;"
                     :: "r"(mbar), "r"(4096u) : "memory");
        asm volatile("cp.async.bulk.shared::cluster.global.mbarrier::complete_tx::bytes "
                     "[%0], [%1], %2, [%3];"
                     :: "r"(xgs_a), "l"((const char*)(xg + (size_t)bx * 1024)), "r"(4096u), "r"(mbar) : "memory");
        __threadfence();
        unsigned a = atomicAdd(&g_bar_count, 1u);
        if (a == NBLK - 1u) { g_bar_count = 0u; st_release(&g_gen, mygen + 1u); }
        else { while (ld_acquire(&g_gen) == mygen) {} }
    }
    mygen++;
    __syncthreads();
    MBAR_WAIT(mbar, 0u);

    // GEMM thread mapping
    const int wm = wid & 1, wn = wid >> 1;        // m16 half, n8 group
    const int lrow = lane & 15, lk = lane >> 4;
    const uint32_t arowoff = (uint32_t)(((wm * 16 + lrow) << 10));
    const int ax7 = lrow & 7;
    const int brow = wn * 8 + (lane & 7);
    const uint32_t browoff = (uint32_t)(brow << 10);
    const int bx7 = brow & 7;
    const int bcs = (lane >> 3) & 1;

    // activation mapping: one (cell, batch) per thread
    const int cl = tid >> 5;          // 0..7
    const int bb = tid & 31;          // batch
    float cst = 0.f;

    for (int t = 0; t < T_; ++t) {
        // 1. bulk copies: h hi+lo (64KB) + xg(t+1) (4KB)
        if (tid == 0) {
            unsigned txb = 65536u + ((t + 1 < T_) ? 4096u : 0u);
            asm volatile("mbarrier.arrive.expect_tx.shared.b64 _, [%0], %1;"
                         :: "r"(mbar), "r"(txb) : "memory");
            asm volatile("cp.async.bulk.shared::cluster.global.mbarrier::complete_tx::bytes "
                         "[%0], [%1], %2, [%3];"
                         :: "r"(bHI), "l"((const char*)g_h2), "r"(65536u), "r"(mbar) : "memory");
            if (t + 1 < T_) {
                const char* xsrc = (const char*)(xg + (((size_t)(t + 1) * NBLK + bx) * 1024));
                asm volatile("cp.async.bulk.shared::cluster.global.mbarrier::complete_tx::bytes "
                             "[%0], [%1], %2, [%3];"
                             :: "r"(xgs_a + (((t + 1) & 1) ? 4096u : 0u)), "l"(xsrc), "r"(4096u), "r"(mbar) : "memory");
            }
        }
        MBAR_WAIT(mbar, (uint32_t)((t + 1) & 1));

        // 2. GEMM: 32 k-steps, 3 independent accumulator chains
        float acc_a[4] = {0.f, 0.f, 0.f, 0.f};   // Whi * hhi
        float acc_b[4] = {0.f, 0.f, 0.f, 0.f};   // Whi * hlo
        float acc_c[4] = {0.f, 0.f, 0.f, 0.f};   // Wlo * hhi
        #pragma unroll 4
        for (int ks = 0; ks < 32; ++ks) {
            uint32_t aoff = (uint32_t)((((ks * 2 + lk) ^ ax7)) << 4);
            uint32_t boff = (uint32_t)((((ks * 2 + bcs) ^ bx7)) << 4);
            uint32_t ah0, ah1, ah2, ah3, al0, al1, al2, al3;
            uint32_t bh0, bh1, bl0, bl1;
            ldmatrix4(ah0, ah1, ah2, ah3, wHI + arowoff + aoff);
            ldmatrix4(al0, al1, al2, al3, wLO + arowoff + aoff);
            ldmatrix2(bh0, bh1, bHI + browoff + boff);
            ldmatrix2(bl0, bl1, bLO + browoff + boff);
            mma16816h(acc_a, ah0, ah1, ah2, ah3, bh0, bh1);
            mma16816h(acc_b, ah0, ah1, ah2, ah3, bl0, bl1);
            mma16816h(acc_c, al0, al1, al2, al3, bh0, bh1);
        }

        // 3. combine + store gates to gsm
        {
            int r0 = wm * 16 + (lane >> 2);
            int cb = wn * 8 + (lane & 3) * 2;
            float s0 = acc_a[0] + acc_b[0] + acc_c[0];
            float s1 = acc_a[1] + acc_b[1] + acc_c[1];
            float s2 = acc_a[2] + acc_b[2] + acc_c[2];
            float s3 = acc_a[3] + acc_b[3] + acc_c[3];
            *(float2*)&gsm[r0 * 34 + cb]       = make_float2(s0, s1);
            *(float2*)&gsm[(r0 + 8) * 34 + cb] = make_float2(s2, s3);
        }
        __syncthreads();

        // 4. activation: one (cell cl, batch bb) per thread, c-state in reg
        {
            const float* xb2 = xgs + ((t & 1) ? 1024 : 0) + bb * 32;
            float gi = gsm[(cl * 4 + 0) * 34 + bb] + xb2[cl];
            float gf = gsm[(cl * 4 + 1) * 34 + bb] + xb2[8 + cl];
            float gg = gsm[(cl * 4 + 2) * 34 + bb] + xb2[16 + cl];
            float go = gsm[(cl * 4 + 3) * 34 + bb] + xb2[24 + cl];
            float iv = sigmoidf(gi);
            float fv = sigmoidf(gf);
            float gv = tanh_fast(gg);
            float ov = sigmoidf(go);
            cst = fv * cst + iv * gv;
            float hv = ov * tanh_fast(cst);
            __half hh = __float2half_rn(hv);
            hsmh[bb * 8 + cl] = hh;
            hsml[bb * 8 + cl] = __float2half_rn(hv - __half2float(hh));
            Y[((size_t)bb * T_ + t) * H_ + bx * 8 + cl] = hv;
        }
        __syncthreads();

        // 5. publish h chunk (bx) of both images
        if (tid < 64) {
            int b = tid >> 1, img = tid & 1;
            const __half* s = img ? hsml : hsmh;
            uint4 v = *(const uint4*)(s + b * 8);
            uint32_t off = (uint32_t)(img * 32768 + (b << 10) + (((bx ^ (b & 7))) << 4));
            *(uint4*)((char*)g_h2 + off) = v;
        }

        // 6. grid barrier
        __syncthreads();
        if (tid == 0) {
            __threadfence();
            unsigned a = atomicAdd(&g_bar_count, 1u);
            if (a == NBLK - 1u) { g_bar_count = 0u; st_release(&g_gen, mygen + 1u); }
            else { while (ld_acquire(&g_gen) == mygen) {} }
        }
        mygen++;
        __syncthreads();
    }
}

// ---------------------------------------------------------------------------
// mean over T + head GEMV
// ---------------------------------------------------------------------------
__global__ void pool_head_kernel(const float* __restrict__ head_w,
                                 const float* __restrict__ head_b,
                                 float* __restrict__ out) {
    int b = blockIdx.x;
    int h = threadIdx.x;
    __shared__ float feat[H_];
    const float* Yp = g_bufB + (size_t)b * T_ * H_;
    float s = 0.f;
    for (int t = 0; t < T_; ++t) s += Yp[t * H_ + h];
    feat[h] = s * (1.0f / (float)T_);
    __syncthreads();
    for (int cc = threadIdx.x; cc < NCLS; cc += blockDim.x) {
        float a = head_b[cc];
        const float* wr = head_w + cc * H_;
        for (int k = 0; k < H_; ++k) a += feat[k] * wr[k];
        out[b * NCLS + cc] = a;
    }
}

// ---------------------------------------------------------------------------
extern "C" void kernel_launch(void* const* d_in, const int* in_sizes, int n_in,
                              void* d_out, int out_size) {
    const float* x     = (const float*)d_in[0];
    const float* convw = (const float*)d_in[1];
    const float* gamma = (const float*)d_in[2];
    const float* beta  = (const float*)d_in[3];

    bool head_first = (in_sizes[4] == NCLS * H_);
    int o = head_first ? 6 : 4;
    const float* headw = (const float*)d_in[head_first ? 4 : 13];
    const float* headb = (const float*)d_in[head_first ? 5 : 14];
    const float* wih[3] = { (const float*)d_in[o + 0], (const float*)d_in[o + 3], (const float*)d_in[o + 6] };
    const float* whh[3] = { (const float*)d_in[o + 1], (const float*)d_in[o + 4], (const float*)d_in[o + 7] };
    const float* bb[3]  = { (const float*)d_in[o + 2], (const float*)d_in[o + 5], (const float*)d_in[o + 8] };

    static int smem_set = 0;
    if (!smem_set) {
        cudaFuncSetAttribute(lstm_kernel, cudaFuncAttributeMaxDynamicSharedMemorySize, SMEM_REQ);
        smem_set = 1;
    }

    void* xgsym = nullptr;   cudaGetSymbolAddress(&xgsym, g_xg);
    void* bufAsym = nullptr; cudaGetSymbolAddress(&bufAsym, g_bufA);
    void* bufBsym = nullptr; cudaGetSymbolAddress(&bufBsym, g_bufB);

    conv_kernel<<<B_ * NF, 128>>>(x, convw);                      // g2
    gn_kernel<<<B_ * GN_G, 256>>>(gamma, beta);                   // g3

    for (int layer = 1; layer <= 3; ++layer) {
        int din = (layer == 1) ? NF : H_;
        dim3 gg(G4H / 128, (B_ * T_) / 128);
        xg_gemm_kernel<<<gg, 256>>>(layer, wih[layer - 1], bb[layer - 1], din);   // g4,...
        float* yptr = (layer == 2) ? (float*)bufAsym : (float*)bufBsym;
        lstm_kernel<<<NBLK, THR, SMEM_REQ>>>(whh[layer - 1], (const float*)xgsym, yptr);  // g5 (layer1)
    }

    pool_head_kernel<<<B_, H_>>>(headw, headb, (float*)d_out);
}

// round 9
// speedup vs baseline: 1.2677x; 1.1402x over previous
#include <cuda_runtime.h>
#include <cuda_bf16.h>
#include <cuda_fp16.h>
#include <cstdint>

// ---------------------------------------------------------------------------
// MetaCNNLSTM: conv1d(64->256,k9,same) + GN(8)+ReLU -> 3x LSTM(512) -> mean -> head(50)
// B=32, T=512.
// LSTM: R6 architecture (proven): 64 persistent blocks, compensated fp16 HMMA
// (3 passes, err~eps^2), atomic+gen grid barrier, bulk-copied operands,
// double-buffered xg prefetch.  NEW: W-hi fragments hoisted into registers.
// xg projection: NEW compensated fp16 HMMA GEMM (was fp32 FFMA).
// ---------------------------------------------------------------------------

#define B_      32
#define CIN     64
#define T_      512
#define NF      256
#define GN_G    8
#define KW      9
#define H_      512
#define G4H     2048
#define NCLS    50

#define NBLK    64
#define THR     256

// lstm dynamic smem layout (byte offsets from 1024-aligned base)
#define SM_WHI   0          // W hi: 32 rows x 64 chunks(16B) fp16, chunk^=(row&7)  32768
#define SM_WLO   32768      // W lo                                                 32768
#define SM_BHI   65536      // h hi: 32 rows x 64 chunks                            32768
#define SM_BLO   98304      // h lo (contiguous: one bulk copy)                     32768
#define SM_GSM   131072     // gates [32][34] fp32                                   4352
#define SM_XGS   135424     // xg staging 2 x [32][32] fp32                          8192
#define SM_HSMH  143616     // h hi staging [32][8] fp16                              512
#define SM_HSML  144128     // h lo staging                                           512
#define SM_MBAR  144640     // mbarrier (8B)
#define SM_TOTAL 144648
#define SMEM_REQ (SM_TOTAL + 1024)

// xg HMMA kernel smem layout
#define XGS_AHI  0          // A hi: 128 rows x 16 chunks(16B), chunk^=(row&7)  32768
#define XGS_ALO  32768
#define XGS_BHI  65536
#define XGS_BLO  98304
#define XG_SMEM_TOTAL 131072
#define XG_SMEM_REQ (XG_SMEM_TOTAL + 1024)

// ---- global scratch ----
__device__ float g_conv[B_ * NF * T_];
__device__ float g_bufA[B_ * T_ * H_];
__device__ float g_bufB[B_ * T_ * H_];
__device__ __align__(4096) float g_xg[T_ * NBLK * B_ * 32];   // [t][blk][b][g*8+cl]
// h images: [0,32KB) hi, [32KB,64KB) lo; row b = 1024B (512 fp16), chunk k16^(b&7)
__device__ __align__(1024) __half g_h2[2 * B_ * H_];
__device__ unsigned g_bar_count;
__device__ unsigned g_gen;

// ---------------------------------------------------------------------------
// helpers
// ---------------------------------------------------------------------------
__device__ __forceinline__ float sigmoidf(float x) { return 1.0f / (1.0f + __expf(-x)); }
__device__ __forceinline__ float tanh_fast(float x) { return 1.0f - 2.0f / (1.0f + __expf(2.0f * x)); }

__device__ __forceinline__ unsigned ld_acquire(unsigned* p) {
    unsigned v;
    asm volatile("ld.acquire.gpu.global.u32 %0, [%1];" : "=r"(v) : "l"(p) : "memory");
    return v;
}
__device__ __forceinline__ void st_release(unsigned* p, unsigned v) {
    asm volatile("st.release.gpu.global.u32 [%0], %1;" :: "l"(p), "r"(v) : "memory");
}
__device__ __forceinline__ uint32_t smem_u32(const void* p) {
    uint32_t a;
    asm("{ .reg .u64 t; cvta.to.shared.u64 t, %1; cvt.u32.u64 %0, t; }" : "=r"(a) : "l"(p));
    return a;
}
// split pair of floats into fp16 hi pack and fp16 lo (residual) pack
__device__ __forceinline__ uint32_t split_pair_h(float a, float b, uint32_t& lo_out) {
    __half ha = __float2half_rn(a), hb = __float2half_rn(b);
    float la = a - __half2float(ha);
    float lb = b - __half2float(hb);
    __half2 lo2 = __halves2half2(__float2half_rn(la), __float2half_rn(lb));
    __half2 hi2 = __halves2half2(ha, hb);
    lo_out = *reinterpret_cast<uint32_t*>(&lo2);
    return *reinterpret_cast<uint32_t*>(&hi2);
}
__device__ __forceinline__ void sts128(uint32_t addr, uint4 v) {
    asm volatile("st.shared.v4.b32 [%0], {%1,%2,%3,%4};"
                 :: "r"(addr), "r"(v.x), "r"(v.y), "r"(v.z), "r"(v.w) : "memory");
}
__device__ __forceinline__ void ldmatrix4(uint32_t& r0, uint32_t& r1, uint32_t& r2, uint32_t& r3, uint32_t addr) {
    asm volatile("ldmatrix.sync.aligned.m8n8.x4.shared.b16 {%0,%1,%2,%3}, [%4];"
                 : "=r"(r0), "=r"(r1), "=r"(r2), "=r"(r3) : "r"(addr));
}
__device__ __forceinline__ void ldmatrix2(uint32_t& r0, uint32_t& r1, uint32_t addr) {
    asm volatile("ldmatrix.sync.aligned.m8n8.x2.shared.b16 {%0,%1}, [%2];"
                 : "=r"(r0), "=r"(r1) : "r"(addr));
}
__device__ __forceinline__ void mma16816h(float* c, const uint32_t* a, uint32_t b0, uint32_t b1) {
    asm volatile("mma.sync.aligned.m16n8k16.row.col.f32.f16.f16.f32 "
                 "{%0,%1,%2,%3}, {%4,%5,%6,%7}, {%8,%9}, {%0,%1,%2,%3};"
                 : "+f"(c[0]), "+f"(c[1]), "+f"(c[2]), "+f"(c[3])
                 : "r"(a[0]), "r"(a[1]), "r"(a[2]), "r"(a[3]), "r"(b0), "r"(b1));
}

#define MBAR_WAIT(mbar, ph) do {                                                   \
    uint32_t _done;                                                                \
    asm volatile("{\n\t.reg .pred p;\n\t"                                          \
        "mbarrier.try_wait.parity.acquire.cta.shared::cta.b64 p, [%1], %2;\n\t"    \
        "selp.b32 %0, 1, 0, p;\n\t}"                                               \
        : "=r"(_done) : "r"(mbar), "r"(ph) : "memory");                            \
    if (!_done) {                                                                  \
        asm volatile("{\n\t.reg .pred P1;\n\t"                                     \
            "WL_%=:\n\t"                                                           \
            "mbarrier.try_wait.parity.acquire.cta.shared::cta.b64 P1, [%0], %1, 0x989680;\n\t" \
            "@P1 bra.uni WD_%=;\n\t"                                               \
            "bra.uni WL_%=;\n\t"                                                   \
            "WD_%=:\n\t}"                                                          \
            :: "r"(mbar), "r"(ph) : "memory");                                     \
    }                                                                              \
} while (0)

// ---------------------------------------------------------------------------
// conv1d
// ---------------------------------------------------------------------------
__global__ void conv_kernel(const float* __restrict__ x, const float* __restrict__ w) {
    int bf = blockIdx.x;
    int b = bf >> 8, f = bf & 255;
    __shared__ float wsh[CIN * KW];
    for (int e = threadIdx.x; e < CIN * KW; e += blockDim.x)
        wsh[e] = w[f * CIN * KW + e];
    __syncthreads();
    const float* xb = x + b * CIN * T_;
    #pragma unroll
    for (int tt = 0; tt < 4; ++tt) {
        int t = tt * 128 + threadIdx.x;
        float acc = 0.f;
        for (int c = 0; c < CIN; ++c) {
            const float* xr = xb + c * T_;
            const float* wr = wsh + c * KW;
            #pragma unroll
            for (int k = 0; k < KW; ++k) {
                int ti = t + k - 4;
                if (ti >= 0 && ti < T_) acc += xr[ti] * wr[k];
            }
        }
        g_conv[(b * NF + f) * T_ + t] = acc;
    }
}

// ---------------------------------------------------------------------------
// fused GroupNorm (stats + apply + ReLU + transpose -> g_bufA)
// ---------------------------------------------------------------------------
__global__ void gn_kernel(const float* __restrict__ gamma, const float* __restrict__ beta) {
    int bg = blockIdx.x;
    int b = bg >> 3, g = bg & 7;
    const float* base = g_conv + (b * NF + g * 32) * T_;
    float s = 0.f, ss = 0.f;
    for (int e = threadIdx.x; e < 32 * T_; e += blockDim.x) {
        float v = base[e];
        s += v; ss += v * v;
    }
    __shared__ float sh_s[256], sh_q[256];
    sh_s[threadIdx.x] = s; sh_q[threadIdx.x] = ss;
    __syncthreads();
    for (int st = 128; st > 0; st >>= 1) {
        if (threadIdx.x < st) {
            sh_s[threadIdx.x] += sh_s[threadIdx.x + st];
            sh_q[threadIdx.x] += sh_q[threadIdx.x + st];
        }
        __syncthreads();
    }
    __shared__ float sh_mu, sh_rs;
    if (threadIdx.x == 0) {
        float n = 32.0f * (float)T_;
        float mu = sh_s[0] / n;
        float var = sh_q[0] / n - mu * mu;
        sh_mu = mu;
        sh_rs = rsqrtf(var + 1e-5f);
    }
    __syncthreads();
    float mu = sh_mu, rs = sh_rs;
    for (int e = threadIdx.x; e < 32 * T_; e += blockDim.x) {
        int cl = e >> 9, t = e & 511;
        int f = g * 32 + cl;
        float v = (base[e] - mu) * rs * gamma[f] + beta[f];
        v = fmaxf(v, 0.f);
        g_bufA[(b * T_ + t) * NF + f] = v;
    }
}

// ---------------------------------------------------------------------------
// xg projection GEMM on HMMA (compensated fp16, 3 passes).
//   C[m, n] = X[m, :] . Wih[n, :] + bias[n]
//   m = t*32 + b (row m of "X" is X[b][t][:]), n = gate*512 + cell
//   output layout: g_xg[((t*64 + blk)*32 + b)*32 + g*8 + cl], blk=cell>>3, cl=cell&7
// Block tile 128(M) x 128(N), K-chunks of 128. 8 warps = 2(M) x 4(N).
// smem rows = 256B (16 chunks of 16B), swizzle chunk ^= (row&7).
// ---------------------------------------------------------------------------
__global__ __launch_bounds__(256) void xg_hmma_kernel(int layer,
                                                      const float* __restrict__ Wih,
                                                      const float* __restrict__ bias,
                                                      int Din) {
    const float* X = (layer == 2) ? g_bufB : g_bufA;
    extern __shared__ char smraw[];
    uint32_t rawa = smem_u32(smraw);
    uint32_t base = (rawa + 1023u) & ~1023u;
    uint32_t aHI = base + XGS_AHI;
    uint32_t aLO = base + XGS_ALO;
    uint32_t bHI = base + XGS_BHI;
    uint32_t bLO = base + XGS_BLO;

    const int tid = threadIdx.x;
    const int wid = tid >> 5, lane = tid & 31;
    const int n0 = blockIdx.x * 128, m0 = blockIdx.y * 128;

    // warp tiling: wm in {0,1} (64 M-rows), wn in {0..3} (32 N-cols)
    const int wm = wid & 1, wn = wid >> 1;
    const int lrow = lane & 15, lk = lane >> 4;
    const int bcs = (lane >> 3) & 1;

    // staging mapping: thread stages row r, column-half hf (64 cols = 8 chunks)
    const int r = tid & 127, hf = tid >> 7;
    const int mg = m0 + r;
    const float* asrc0 = X + ((size_t)(mg & 31) * T_ + (mg >> 5)) * Din + hf * 64;
    const float* bsrc0 = Wih + (size_t)(n0 + r) * Din + hf * 64;
    const uint32_t stoff0 = (uint32_t)(r * 256);

    float acc[4][4][4];
    #pragma unroll
    for (int mi = 0; mi < 4; ++mi)
        #pragma unroll
        for (int ni = 0; ni < 4; ++ni)
            #pragma unroll
            for (int q = 0; q < 4; ++q) acc[mi][ni][q] = 0.f;

    const int nchunks = Din >> 7;        // 2 (layer 1) or 4
    for (int kc = 0; kc < nchunks; ++kc) {
        // ---- stage A & B chunk (fp32 -> fp16 hi/lo, swizzled) ----
        const float* asrc = asrc0 + kc * 128;
        const float* bsrc = bsrc0 + kc * 128;
        #pragma unroll
        for (int j = 0; j < 8; ++j) {
            int c = hf * 8 + j;
            uint32_t off = stoff0 + (uint32_t)(((c ^ (r & 7))) << 4);
            {
                float4 f0 = *(const float4*)(asrc + j * 8);
                float4 f1 = *(const float4*)(asrc + j * 8 + 4);
                uint4 vh, vl;
                vh.x = split_pair_h(f0.x, f0.y, vl.x);
                vh.y = split_pair_h(f0.z, f0.w, vl.y);
                vh.z = split_pair_h(f1.x, f1.y, vl.z);
                vh.w = split_pair_h(f1.z, f1.w, vl.w);
                sts128(aHI + off, vh);
                sts128(aLO + off, vl);
            }
            {
                float4 f0 = *(const float4*)(bsrc + j * 8);
                float4 f1 = *(const float4*)(bsrc + j * 8 + 4);
                uint4 vh, vl;
                vh.x = split_pair_h(f0.x, f0.y, vl.x);
                vh.y = split_pair_h(f0.z, f0.w, vl.y);
                vh.z = split_pair_h(f1.x, f1.y, vl.z);
                vh.w = split_pair_h(f1.z, f1.w, vl.w);
                sts128(bHI + off, vh);
                sts128(bLO + off, vl);
            }
        }
        __syncthreads();

        // ---- MMA over 8 k16-steps ----
        #pragma unroll
        for (int s = 0; s < 8; ++s) {
            uint32_t ahf[4][4], alf[4][4], bhf[4][2], blf[4][2];
            #pragma unroll
            for (int mi = 0; mi < 4; ++mi) {
                int rowA = wm * 64 + mi * 16 + lrow;
                uint32_t aoff = (uint32_t)(rowA * 256 + (((2 * s + lk) ^ (rowA & 7)) << 4));
                ldmatrix4(ahf[mi][0], ahf[mi][1], ahf[mi][2], ahf[mi][3], aHI + aoff);
                ldmatrix4(alf[mi][0], alf[mi][1], alf[mi][2], alf[mi][3], aLO + aoff);
            }
            #pragma unroll
            for (int ni = 0; ni < 4; ++ni) {
                int rowB = wn * 32 + ni * 8 + (lane & 7);
                uint32_t boff = (uint32_t)(rowB * 256 + (((2 * s + bcs) ^ (rowB & 7)) << 4));
                ldmatrix2(bhf[ni][0], bhf[ni][1], bHI + boff);
                ldmatrix2(blf[ni][0], blf[ni][1], bLO + boff);
            }
            #pragma unroll
            for (int mi = 0; mi < 4; ++mi)
                #pragma unroll
                for (int ni = 0; ni < 4; ++ni) {
                    mma16816h(acc[mi][ni], ahf[mi], bhf[ni][0], bhf[ni][1]);
                    mma16816h(acc[mi][ni], ahf[mi], blf[ni][0], blf[ni][1]);
                    mma16816h(acc[mi][ni], alf[mi], bhf[ni][0], bhf[ni][1]);
                }
        }
        __syncthreads();
    }

    // ---- epilogue: bias + scatter to g_xg layout ----
    #pragma unroll
    for (int mi = 0; mi < 4; ++mi) {
        #pragma unroll
        for (int ni = 0; ni < 4; ++ni) {
            int cb = n0 + wn * 32 + ni * 8 + (lane & 3) * 2;
            int g = cb >> 9, cell = cb & 511;
            int blk = cell >> 3, cl = cell & 7;
            float bz0 = bias[cb], bz1 = bias[cb + 1];
            #pragma unroll
            for (int hrow = 0; hrow < 2; ++hrow) {
                int row = m0 + wm * 64 + mi * 16 + (lane >> 2) + hrow * 8;
                int t = row >> 5, b = row & 31;
                float2 v = make_float2(acc[mi][ni][hrow * 2 + 0] + bz0,
                                       acc[mi][ni][hrow * 2 + 1] + bz1);
                *(float2*)&g_xg[(((size_t)t * NBLK + blk) * 32 + b) * 32 + g * 8 + cl] = v;
            }
        }
    }
}

// ---------------------------------------------------------------------------
// persistent HMMA LSTM (R6-proven): 64 blocks, block bx owns cells
// [bx*8, bx*8+8). A row r <-> (gate=r&3, cell=bx*8+(r>>2)). B row = batch.
// warps: wm = wid&1 (m16 half), wn = wid>>1 (n8 group).
// NEW: W-hi fragments hoisted into registers for all 512 steps.
// ---------------------------------------------------------------------------
__global__ __launch_bounds__(THR, 1) void lstm_kernel(const float* __restrict__ Whh,
                                                      const float* __restrict__ xg,
                                                      float* __restrict__ Y) {
    extern __shared__ char smraw[];
    uint32_t rawa = smem_u32(smraw);
    uint32_t base = (rawa + 1023u) & ~1023u;
    char* sbase = smraw + (base - rawa);
    uint32_t wHI  = base + SM_WHI;
    uint32_t wLO  = base + SM_WLO;
    uint32_t bHI  = base + SM_BHI;
    uint32_t bLO  = base + SM_BLO;
    float*   gsm  = (float*)(sbase + SM_GSM);
    float*   xgs  = (float*)(sbase + SM_XGS);
    __half*  hsmh = (__half*)(sbase + SM_HSMH);
    __half*  hsml = (__half*)(sbase + SM_HSML);
    uint32_t mbar = base + SM_MBAR;
    uint32_t xgs_a = base + SM_XGS;

    const int tid = threadIdx.x;
    const int bx = blockIdx.x;
    const int wid = tid >> 5, lane = tid & 31;

    unsigned mygen = *((volatile unsigned*)&g_gen);

    if (tid == 0) {
        asm volatile("mbarrier.init.shared.b64 [%0], %1;" :: "r"(mbar), "r"(1u) : "memory");
    }

    // --- stage W tile: 32 rows x 64 chunks(16B), fp32 -> fp16 hi/lo, chunk^=(row&7) ---
    #pragma unroll
    for (int i = 0; i < 8; ++i) {
        int g = tid + i * 256;            // 2048 chunks
        int r = g >> 6, k16 = g & 63;
        int j = (r & 3) * 512 + bx * 8 + (r >> 2);
        const float* src = Whh + (size_t)j * 512 + k16 * 8;
        float4 f0 = *(const float4*)(src);
        float4 f1 = *(const float4*)(src + 4);
        uint4 vh, vl;
        vh.x = split_pair_h(f0.x, f0.y, vl.x);
        vh.y = split_pair_h(f0.z, f0.w, vl.y);
        vh.z = split_pair_h(f1.x, f1.y, vl.z);
        vh.w = split_pair_h(f1.z, f1.w, vl.w);
        uint32_t off = (uint32_t)((r << 10) + (((k16 ^ (r & 7))) << 4));
        sts128(wHI + off, vh);
        sts128(wLO + off, vl);
    }

    // --- zero this block's chunk (index bx) of both g_h2 images ---
    if (tid < 64) {
        int b = tid >> 1, img = tid & 1;
        uint32_t off = (uint32_t)(img * 32768 + (b << 10) + (((bx ^ (b & 7))) << 4));
        *(uint4*)((char*)g_h2 + off) = make_uint4(0, 0, 0, 0);
    }
    __syncthreads();

    // GEMM thread mapping
    const int wm = wid & 1, wn = wid >> 1;        // m16 half, n8 group
    const int lrow = lane & 15, lk = lane >> 4;
    const uint32_t arowoff = (uint32_t)(((wm * 16 + lrow) << 10));
    const int ax7 = lrow & 7;

    // --- hoist W-hi fragments into registers for the whole t-loop ---
    uint32_t AH[32][4];
    #pragma unroll
    for (int ks = 0; ks < 32; ++ks) {
        uint32_t aoff = (uint32_t)((((ks * 2 + lk) ^ ax7)) << 4);
        ldmatrix4(AH[ks][0], AH[ks][1], AH[ks][2], AH[ks][3], wHI + arowoff + aoff);
    }

    // --- prologue: prefetch xg(0) into buffer 0 + initial grid barrier ---
    if (tid == 0) {
        asm volatile("mbarrier.arrive.expect_tx.shared.b64 _, [%0], %1;"
                     :: "r"(mbar), "r"(4096u) : "memory");
        asm volatile("cp.async.bulk.shared::cluster.global.mbarrier::complete_tx::bytes "
                     "[%0], [%1], %2, [%3];"
                     :: "r"(xgs_a), "l"((const char*)(xg + (size_t)bx * 1024)), "r"(4096u), "r"(mbar) : "memory");
        __threadfence();
        unsigned a = atomicAdd(&g_bar_count, 1u);
        if (a == NBLK - 1u) { g_bar_count = 0u; st_release(&g_gen, mygen + 1u); }
        else { while (ld_acquire(&g_gen) == mygen) {} }
    }
    mygen++;
    __syncthreads();
    MBAR_WAIT(mbar, 0u);

    // B-frag addressing
    const int brow = wn * 8 + (lane & 7);
    const uint32_t browoff = (uint32_t)(brow << 10);
    const int bx7 = brow & 7;
    const int bcs = (lane >> 3) & 1;

    // activation mapping: cl = tid>>5 (0..7), b = tid&31
    const int cl = tid >> 5;
    const int bb = tid & 31;
    float cst = 0.f;

    for (int t = 0; t < T_; ++t) {
        // 1. bulk copies: h hi+lo (64KB) + xg(t+1) (4KB)
        if (tid == 0) {
            unsigned txb = 65536u + ((t + 1 < T_) ? 4096u : 0u);
            asm volatile("mbarrier.arrive.expect_tx.shared.b64 _, [%0], %1;"
                         :: "r"(mbar), "r"(txb) : "memory");
            asm volatile("cp.async.bulk.shared::cluster.global.mbarrier::complete_tx::bytes "
                         "[%0], [%1], %2, [%3];"
                         :: "r"(bHI), "l"((const char*)g_h2), "r"(65536u), "r"(mbar) : "memory");
            if (t + 1 < T_) {
                const char* xsrc = (const char*)(xg + (((size_t)(t + 1) * NBLK + bx) * 1024));
                asm volatile("cp.async.bulk.shared::cluster.global.mbarrier::complete_tx::bytes "
                             "[%0], [%1], %2, [%3];"
                             :: "r"(xgs_a + (((t + 1) & 1) ? 4096u : 0u)), "l"(xsrc), "r"(4096u), "r"(mbar) : "memory");
            }
        }
        MBAR_WAIT(mbar, (uint32_t)((t + 1) & 1));

        // 2. GEMM: 32 k-steps, W-hi in registers, 3 accumulator chains
        float acc_a[4] = {0.f, 0.f, 0.f, 0.f};   // Whi * hhi
        float acc_b[4] = {0.f, 0.f, 0.f, 0.f};   // Whi * hlo
        float acc_c[4] = {0.f, 0.f, 0.f, 0.f};   // Wlo * hhi
        #pragma unroll
        for (int ks = 0; ks < 32; ++ks) {
            uint32_t aoff = (uint32_t)((((ks * 2 + lk) ^ ax7)) << 4);
            uint32_t boff = (uint32_t)((((ks * 2 + bcs) ^ bx7)) << 4);
            uint32_t al0, al1, al2, al3;
            uint32_t bh0, bh1, bl0, bl1;
            ldmatrix4(al0, al1, al2, al3, wLO + arowoff + aoff);
            ldmatrix2(bh0, bh1, bHI + browoff + boff);
            ldmatrix2(bl0, bl1, bLO + browoff + boff);
            mma16816h(acc_a, AH[ks], bh0, bh1);
            mma16816h(acc_b, AH[ks], bl0, bl1);
            uint32_t alr[4] = {al0, al1, al2, al3};
            mma16816h(acc_c, alr, bh0, bh1);
        }

        // 3. combine + store gates to gsm
        {
            int r0 = wm * 16 + (lane >> 2);
            int cb = wn * 8 + (lane & 3) * 2;
            float s0 = acc_a[0] + acc_b[0] + acc_c[0];
            float s1 = acc_a[1] + acc_b[1] + acc_c[1];
            float s2 = acc_a[2] + acc_b[2] + acc_c[2];
            float s3 = acc_a[3] + acc_b[3] + acc_c[3];
            *(float2*)&gsm[r0 * 34 + cb]       = make_float2(s0, s1);
            *(float2*)&gsm[(r0 + 8) * 34 + cb] = make_float2(s2, s3);
        }
        __syncthreads();

        // 4. activation: one (cell cl, batch bb) per thread, c-state in reg
        {
            const float* xb2 = xgs + ((t & 1) ? 1024 : 0) + bb * 32;
            float gi = gsm[(cl * 4 + 0) * 34 + bb] + xb2[cl];
            float gf = gsm[(cl * 4 + 1) * 34 + bb] + xb2[8 + cl];
            float gg = gsm[(cl * 4 + 2) * 34 + bb] + xb2[16 + cl];
            float go = gsm[(cl * 4 + 3) * 34 + bb] + xb2[24 + cl];
            float iv = sigmoidf(gi);
            float fv = sigmoidf(gf);
            float gv = tanh_fast(gg);
            float ov = sigmoidf(go);
            cst = fv * cst + iv * gv;
            float hv = ov * tanh_fast(cst);
            __half hh = __float2half_rn(hv);
            hsmh[bb * 8 + cl] = hh;
            hsml[bb * 8 + cl] = __float2half_rn(hv - __half2float(hh));
            Y[((size_t)bb * T_ + t) * H_ + bx * 8 + cl] = hv;
        }
        __syncthreads();

        // 5. publish h chunk (bx) of both images
        if (tid < 64) {
            int b = tid >> 1, img = tid & 1;
            const __half* s = img ? hsml : hsmh;
            uint4 v = *(const uint4*)(s + b * 8);
            uint32_t off = (uint32_t)(img * 32768 + (b << 10) + (((bx ^ (b & 7))) << 4));
            *(uint4*)((char*)g_h2 + off) = v;
        }

        // 6. grid barrier
        __syncthreads();
        if (tid == 0) {
            __threadfence();
            unsigned a = atomicAdd(&g_bar_count, 1u);
            if (a == NBLK - 1u) { g_bar_count = 0u; st_release(&g_gen, mygen + 1u); }
            else { while (ld_acquire(&g_gen) == mygen) {} }
        }
        mygen++;
        __syncthreads();
    }
}

// ---------------------------------------------------------------------------
// mean over T + head GEMV
// ---------------------------------------------------------------------------
__global__ void pool_head_kernel(const float* __restrict__ head_w,
                                 const float* __restrict__ head_b,
                                 float* __restrict__ out) {
    int b = blockIdx.x;
    int h = threadIdx.x;
    __shared__ float feat[H_];
    const float* Yp = g_bufB + (size_t)b * T_ * H_;
    float s = 0.f;
    for (int t = 0; t < T_; ++t) s += Yp[t * H_ + h];
    feat[h] = s * (1.0f / (float)T_);
    __syncthreads();
    for (int cc = threadIdx.x; cc < NCLS; cc += blockDim.x) {
        float a = head_b[cc];
        const float* wr = head_w + cc * H_;
        for (int k = 0; k < H_; ++k) a += feat[k] * wr[k];
        out[b * NCLS + cc] = a;
    }
}

// ---------------------------------------------------------------------------
extern "C" void kernel_launch(void* const* d_in, const int* in_sizes, int n_in,
                              void* d_out, int out_size) {
    const float* x     = (const float*)d_in[0];
    const float* convw = (const float*)d_in[1];
    const float* gamma = (const float*)d_in[2];
    const float* beta  = (const float*)d_in[3];

    bool head_first = (in_sizes[4] == NCLS * H_);
    int o = head_first ? 6 : 4;
    const float* headw = (const float*)d_in[head_first ? 4 : 13];
    const float* headb = (const float*)d_in[head_first ? 5 : 14];
    const float* wih[3] = { (const float*)d_in[o + 0], (const float*)d_in[o + 3], (const float*)d_in[o + 6] };
    const float* whh[3] = { (const float*)d_in[o + 1], (const float*)d_in[o + 4], (const float*)d_in[o + 7] };
    const float* bb[3]  = { (const float*)d_in[o + 2], (const float*)d_in[o + 5], (const float*)d_in[o + 8] };

    static int smem_set = 0;
    if (!smem_set) {
        cudaFuncSetAttribute(lstm_kernel, cudaFuncAttributeMaxDynamicSharedMemorySize, SMEM_REQ);
        cudaFuncSetAttribute(xg_hmma_kernel, cudaFuncAttributeMaxDynamicSharedMemorySize, XG_SMEM_REQ);
        smem_set = 1;
    }

    void* xgsym = nullptr;   cudaGetSymbolAddress(&xgsym, g_xg);
    void* bufAsym = nullptr; cudaGetSymbolAddress(&bufAsym, g_bufA);
    void* bufBsym = nullptr; cudaGetSymbolAddress(&bufBsym, g_bufB);

    conv_kernel<<<B_ * NF, 128>>>(x, convw);
    gn_kernel<<<B_ * GN_G, 256>>>(gamma, beta);

    for (int layer = 1; layer <= 3; ++layer) {
        int din = (layer == 1) ? NF : H_;
        dim3 gg(G4H / 128, (B_ * T_) / 128);
        xg_hmma_kernel<<<gg, 256, XG_SMEM_REQ>>>(layer, wih[layer - 1], bb[layer - 1], din);
        float* yptr = (layer == 2) ? (float*)bufAsym : (float*)bufBsym;
        lstm_kernel<<<NBLK, THR, SMEM_REQ>>>(whh[layer - 1], (const float*)xgsym, yptr);
    }

    pool_head_kernel<<<B_, H_>>>(headw, headb, (float*)d_out);
}

// round 10
// speedup vs baseline: 1.5819x; 1.2478x over previous
#include <cuda_runtime.h>
#include <cuda_bf16.h>
#include <cuda_fp16.h>
#include <cstdint>

// ---------------------------------------------------------------------------
// MetaCNNLSTM: conv1d(64->256,k9,same) + GN(8)+ReLU -> 3x LSTM(512) -> mean -> head(50)
// B=32, T=512.
// LSTM: batch split into 2 independent groups of 16; each group = 64 persistent
// blocks (8 cells each) with its own atomic+gen barrier (R6/R9-proven protocol).
// Compensated fp16 HMMA (3 passes), W-hi fragments in registers, warps split
// 2m x 2n x 2k-halves, bulk-copied operands, double-buffered xg prefetch.
// ---------------------------------------------------------------------------

#define B_      32
#define CIN     64
#define T_      512
#define NF      256
#define GN_G    8
#define KW      9
#define H_      512
#define G4H     2048
#define NCLS    50

#define NBLK    128            // 2 groups x 64 blocks
#define GRP     64
#define THR     256

// lstm dynamic smem layout (byte offsets from 1024-aligned base)
#define SM_WHI   0          // W hi: 32 rows x 64 chunks(16B) fp16, chunk^=(row&7)  32768
#define SM_WLO   32768      // W lo                                                 32768
#define SM_BHI   65536      // h hi: 16 rows x 64 chunks                            16384
#define SM_BLO   81920      // h lo (contiguous: one bulk copy)                     16384
#define SM_GSM   98304      // gates 2(k-half) x [32][18] fp32                       4608
#define SM_XGS   102912     // xg staging 2 x [16][32] fp32                          4096
#define SM_HSMH  107008     // h hi staging [16][8] fp16                              256
#define SM_HSML  107264     // h lo staging                                           256
#define SM_MBAR  107520     // mbarrier (8B)
#define SM_TOTAL 107528
#define SMEM_REQ (SM_TOTAL + 1024)

// xg HMMA kernel smem layout
#define XGS_AHI  0          // A hi: 128 rows x 16 chunks(16B), chunk^=(row&7)  32768
#define XGS_ALO  32768
#define XGS_BHI  65536
#define XGS_BLO  98304
#define XG_SMEM_TOTAL 131072
#define XG_SMEM_REQ (XG_SMEM_TOTAL + 1024)

// ---- global scratch ----
__device__ float g_conv[B_ * NF * T_];
__device__ float g_bufA[B_ * T_ * H_];
__device__ float g_bufB[B_ * T_ * H_];
// [t][blk(128)][b_local(16)][gate*8+cl]  -- 2KB per (t, blk)
__device__ __align__(4096) float g_xg[T_ * NBLK * 16 * 32];
// h: [group(2)][img(2)][b_local(16) rows of 1024B, chunk k16^(b&7)] = 2 x 32KB
__device__ __align__(1024) __half g_h2[2 * 2 * 16 * H_];
__device__ unsigned g_barc[2];
__device__ unsigned g_gen2[2];

// ---------------------------------------------------------------------------
// helpers
// ---------------------------------------------------------------------------
__device__ __forceinline__ float sigmoidf(float x) { return 1.0f / (1.0f + __expf(-x)); }
__device__ __forceinline__ float tanh_fast(float x) { return 1.0f - 2.0f / (1.0f + __expf(2.0f * x)); }

__device__ __forceinline__ unsigned ld_acquire(unsigned* p) {
    unsigned v;
    asm volatile("ld.acquire.gpu.global.u32 %0, [%1];" : "=r"(v) : "l"(p) : "memory");
    return v;
}
__device__ __forceinline__ void st_release(unsigned* p, unsigned v) {
    asm volatile("st.release.gpu.global.u32 [%0], %1;" :: "l"(p), "r"(v) : "memory");
}
__device__ __forceinline__ uint32_t smem_u32(const void* p) {
    uint32_t a;
    asm("{ .reg .u64 t; cvta.to.shared.u64 t, %1; cvt.u32.u64 %0, t; }" : "=r"(a) : "l"(p));
    return a;
}
__device__ __forceinline__ uint32_t split_pair_h(float a, float b, uint32_t& lo_out) {
    __half ha = __float2half_rn(a), hb = __float2half_rn(b);
    float la = a - __half2float(ha);
    float lb = b - __half2float(hb);
    __half2 lo2 = __halves2half2(__float2half_rn(la), __float2half_rn(lb));
    __half2 hi2 = __halves2half2(ha, hb);
    lo_out = *reinterpret_cast<uint32_t*>(&lo2);
    return *reinterpret_cast<uint32_t*>(&hi2);
}
__device__ __forceinline__ void sts128(uint32_t addr, uint4 v) {
    asm volatile("st.shared.v4.b32 [%0], {%1,%2,%3,%4};"
                 :: "r"(addr), "r"(v.x), "r"(v.y), "r"(v.z), "r"(v.w) : "memory");
}
__device__ __forceinline__ void ldmatrix4(uint32_t& r0, uint32_t& r1, uint32_t& r2, uint32_t& r3, uint32_t addr) {
    asm volatile("ldmatrix.sync.aligned.m8n8.x4.shared.b16 {%0,%1,%2,%3}, [%4];"
                 : "=r"(r0), "=r"(r1), "=r"(r2), "=r"(r3) : "r"(addr));
}
__device__ __forceinline__ void ldmatrix2(uint32_t& r0, uint32_t& r1, uint32_t addr) {
    asm volatile("ldmatrix.sync.aligned.m8n8.x2.shared.b16 {%0,%1}, [%2];"
                 : "=r"(r0), "=r"(r1) : "r"(addr));
}
__device__ __forceinline__ void mma16816h(float* c, const uint32_t* a, uint32_t b0, uint32_t b1) {
    asm volatile("mma.sync.aligned.m16n8k16.row.col.f32.f16.f16.f32 "
                 "{%0,%1,%2,%3}, {%4,%5,%6,%7}, {%8,%9}, {%0,%1,%2,%3};"
                 : "+f"(c[0]), "+f"(c[1]), "+f"(c[2]), "+f"(c[3])
                 : "r"(a[0]), "r"(a[1]), "r"(a[2]), "r"(a[3]), "r"(b0), "r"(b1));
}

#define MBAR_WAIT(mbar, ph) do {                                                   \
    uint32_t _done;                                                                \
    asm volatile("{\n\t.reg .pred p;\n\t"                                          \
        "mbarrier.try_wait.parity.acquire.cta.shared::cta.b64 p, [%1], %2;\n\t"    \
        "selp.b32 %0, 1, 0, p;\n\t}"                                               \
        : "=r"(_done) : "r"(mbar), "r"(ph) : "memory");                            \
    if (!_done) {                                                                  \
        asm volatile("{\n\t.reg .pred P1;\n\t"                                     \
            "WL_%=:\n\t"                                                           \
            "mbarrier.try_wait.parity.acquire.cta.shared::cta.b64 P1, [%0], %1, 0x989680;\n\t" \
            "@P1 bra.uni WD_%=;\n\t"                                               \
            "bra.uni WL_%=;\n\t"                                                   \
            "WD_%=:\n\t}"                                                          \
            :: "r"(mbar), "r"(ph) : "memory");                                     \
    }                                                                              \
} while (0)

// ---------------------------------------------------------------------------
// conv1d
// ---------------------------------------------------------------------------
__global__ void conv_kernel(const float* __restrict__ x, const float* __restrict__ w) {
    int bf = blockIdx.x;
    int b = bf >> 8, f = bf & 255;
    __shared__ float wsh[CIN * KW];
    for (int e = threadIdx.x; e < CIN * KW; e += blockDim.x)
        wsh[e] = w[f * CIN * KW + e];
    __syncthreads();
    const float* xb = x + b * CIN * T_;
    #pragma unroll
    for (int tt = 0; tt < 4; ++tt) {
        int t = tt * 128 + threadIdx.x;
        float acc = 0.f;
        for (int c = 0; c < CIN; ++c) {
            const float* xr = xb + c * T_;
            const float* wr = wsh + c * KW;
            #pragma unroll
            for (int k = 0; k < KW; ++k) {
                int ti = t + k - 4;
                if (ti >= 0 && ti < T_) acc += xr[ti] * wr[k];
            }
        }
        g_conv[(b * NF + f) * T_ + t] = acc;
    }
}

// ---------------------------------------------------------------------------
// fused GroupNorm (stats + apply + ReLU + transpose -> g_bufA)
// ---------------------------------------------------------------------------
__global__ void gn_kernel(const float* __restrict__ gamma, const float* __restrict__ beta) {
    int bg = blockIdx.x;
    int b = bg >> 3, g = bg & 7;
    const float* base = g_conv + (b * NF + g * 32) * T_;
    float s = 0.f, ss = 0.f;
    for (int e = threadIdx.x; e < 32 * T_; e += blockDim.x) {
        float v = base[e];
        s += v; ss += v * v;
    }
    __shared__ float sh_s[256], sh_q[256];
    sh_s[threadIdx.x] = s; sh_q[threadIdx.x] = ss;
    __syncthreads();
    for (int st = 128; st > 0; st >>= 1) {
        if (threadIdx.x < st) {
            sh_s[threadIdx.x] += sh_s[threadIdx.x + st];
            sh_q[threadIdx.x] += sh_q[threadIdx.x + st];
        }
        __syncthreads();
    }
    __shared__ float sh_mu, sh_rs;
    if (threadIdx.x == 0) {
        float n = 32.0f * (float)T_;
        float mu = sh_s[0] / n;
        float var = sh_q[0] / n - mu * mu;
        sh_mu = mu;
        sh_rs = rsqrtf(var + 1e-5f);
    }
    __syncthreads();
    float mu = sh_mu, rs = sh_rs;
    for (int e = threadIdx.x; e < 32 * T_; e += blockDim.x) {
        int cl = e >> 9, t = e & 511;
        int f = g * 32 + cl;
        float v = (base[e] - mu) * rs * gamma[f] + beta[f];
        v = fmaxf(v, 0.f);
        g_bufA[(b * T_ + t) * NF + f] = v;
    }
}

// ---------------------------------------------------------------------------
// xg projection GEMM on HMMA (compensated fp16, 3 passes).
// output: g_xg[((t*128 + blk)*16 + b_local)*32 + gate*8 + cl]
//   blk = (b>>4)*64 + (cell>>3), b_local = b&15, cl = cell&7
// ---------------------------------------------------------------------------
__global__ __launch_bounds__(256) void xg_hmma_kernel(int layer,
                                                      const float* __restrict__ Wih,
                                                      const float* __restrict__ bias,
                                                      int Din) {
    const float* X = (layer == 2) ? g_bufB : g_bufA;
    extern __shared__ char smraw[];
    uint32_t rawa = smem_u32(smraw);
    uint32_t base = (rawa + 1023u) & ~1023u;
    uint32_t aHI = base + XGS_AHI;
    uint32_t aLO = base + XGS_ALO;
    uint32_t bHI = base + XGS_BHI;
    uint32_t bLO = base + XGS_BLO;

    const int tid = threadIdx.x;
    const int wid = tid >> 5, lane = tid & 31;
    const int n0 = blockIdx.x * 128, m0 = blockIdx.y * 128;

    const int wm = wid & 1, wn = wid >> 1;
    const int lrow = lane & 15, lk = lane >> 4;
    const int bcs = (lane >> 3) & 1;

    const int r = tid & 127, hf = tid >> 7;
    const int mg = m0 + r;
    const float* asrc0 = X + ((size_t)(mg & 31) * T_ + (mg >> 5)) * Din + hf * 64;
    const float* bsrc0 = Wih + (size_t)(n0 + r) * Din + hf * 64;
    const uint32_t stoff0 = (uint32_t)(r * 256);

    float acc[4][4][4];
    #pragma unroll
    for (int mi = 0; mi < 4; ++mi)
        #pragma unroll
        for (int ni = 0; ni < 4; ++ni)
            #pragma unroll
            for (int q = 0; q < 4; ++q) acc[mi][ni][q] = 0.f;

    const int nchunks = Din >> 7;
    for (int kc = 0; kc < nchunks; ++kc) {
        const float* asrc = asrc0 + kc * 128;
        const float* bsrc = bsrc0 + kc * 128;
        #pragma unroll
        for (int j = 0; j < 8; ++j) {
            int c = hf * 8 + j;
            uint32_t off = stoff0 + (uint32_t)(((c ^ (r & 7))) << 4);
            {
                float4 f0 = *(const float4*)(asrc + j * 8);
                float4 f1 = *(const float4*)(asrc + j * 8 + 4);
                uint4 vh, vl;
                vh.x = split_pair_h(f0.x, f0.y, vl.x);
                vh.y = split_pair_h(f0.z, f0.w, vl.y);
                vh.z = split_pair_h(f1.x, f1.y, vl.z);
                vh.w = split_pair_h(f1.z, f1.w, vl.w);
                sts128(aHI + off, vh);
                sts128(aLO + off, vl);
            }
            {
                float4 f0 = *(const float4*)(bsrc + j * 8);
                float4 f1 = *(const float4*)(bsrc + j * 8 + 4);
                uint4 vh, vl;
                vh.x = split_pair_h(f0.x, f0.y, vl.x);
                vh.y = split_pair_h(f0.z, f0.w, vl.y);
                vh.z = split_pair_h(f1.x, f1.y, vl.z);
                vh.w = split_pair_h(f1.z, f1.w, vl.w);
                sts128(bHI + off, vh);
                sts128(bLO + off, vl);
            }
        }
        __syncthreads();

        #pragma unroll
        for (int s = 0; s < 8; ++s) {
            uint32_t ahf[4][4], alf[4][4], bhf[4][2], blf[4][2];
            #pragma unroll
            for (int mi = 0; mi < 4; ++mi) {
                int rowA = wm * 64 + mi * 16 + lrow;
                uint32_t aoff = (uint32_t)(rowA * 256 + (((2 * s + lk) ^ (rowA & 7)) << 4));
                ldmatrix4(ahf[mi][0], ahf[mi][1], ahf[mi][2], ahf[mi][3], aHI + aoff);
                ldmatrix4(alf[mi][0], alf[mi][1], alf[mi][2], alf[mi][3], aLO + aoff);
            }
            #pragma unroll
            for (int ni = 0; ni < 4; ++ni) {
                int rowB = wn * 32 + ni * 8 + (lane & 7);
                uint32_t boff = (uint32_t)(rowB * 256 + (((2 * s + bcs) ^ (rowB & 7)) << 4));
                ldmatrix2(bhf[ni][0], bhf[ni][1], bHI + boff);
                ldmatrix2(blf[ni][0], blf[ni][1], bLO + boff);
            }
            #pragma unroll
            for (int mi = 0; mi < 4; ++mi)
                #pragma unroll
                for (int ni = 0; ni < 4; ++ni) {
                    mma16816h(acc[mi][ni], ahf[mi], bhf[ni][0], bhf[ni][1]);
                    mma16816h(acc[mi][ni], ahf[mi], blf[ni][0], blf[ni][1]);
                    mma16816h(acc[mi][ni], alf[mi], bhf[ni][0], bhf[ni][1]);
                }
        }
        __syncthreads();
    }

    // epilogue: bias + scatter (block-contiguous group layout)
    #pragma unroll
    for (int mi = 0; mi < 4; ++mi) {
        #pragma unroll
        for (int ni = 0; ni < 4; ++ni) {
            int cb = n0 + wn * 32 + ni * 8 + (lane & 3) * 2;
            int gate = cb >> 9, cell = cb & 511;
            int cblk = cell >> 3, cl = cell & 7;
            float bz0 = bias[cb], bz1 = bias[cb + 1];
            #pragma unroll
            for (int hrow = 0; hrow < 2; ++hrow) {
                int row = m0 + wm * 64 + mi * 16 + (lane >> 2) + hrow * 8;
                int t = row >> 5, b = row & 31;
                int blk = (b >> 4) * 64 + cblk;
                float2 v = make_float2(acc[mi][ni][hrow * 2 + 0] + bz0,
                                       acc[mi][ni][hrow * 2 + 1] + bz1);
                *(float2*)&g_xg[(((size_t)t * NBLK + blk) * 16 + (b & 15)) * 32 + gate * 8 + cl] = v;
            }
        }
    }
}

// ---------------------------------------------------------------------------
// persistent HMMA LSTM: 2 groups x 64 blocks. Block bx: group g=bx>>6 (batches
// g*16..+16), cells (bx&63)*8..+8. A row r <-> (gate=r&3, cell=c0+(r>>2)).
// 8 warps = 2(m16) x 2(n8) x 2(k-half); k-halves reduced in smem.
// ---------------------------------------------------------------------------
__global__ __launch_bounds__(THR, 1) void lstm_kernel(const float* __restrict__ Whh,
                                                      const float* __restrict__ xg,
                                                      float* __restrict__ Y) {
    extern __shared__ char smraw[];
    uint32_t rawa = smem_u32(smraw);
    uint32_t base = (rawa + 1023u) & ~1023u;
    char* sbase = smraw + (base - rawa);
    uint32_t wHI  = base + SM_WHI;
    uint32_t wLO  = base + SM_WLO;
    uint32_t bHI  = base + SM_BHI;
    float*   gsm  = (float*)(sbase + SM_GSM);
    float*   xgs  = (float*)(sbase + SM_XGS);
    __half*  hsmh = (__half*)(sbase + SM_HSMH);
    __half*  hsml = (__half*)(sbase + SM_HSML);
    uint32_t mbar = base + SM_MBAR;
    uint32_t xgs_a = base + SM_XGS;

    const int tid = threadIdx.x;
    const int bx = blockIdx.x;
    const int g  = bx >> 6;            // batch group
    const int ci = bx & 63;            // cell-block index
    const int c0 = ci * 8;
    const int wid = tid >> 5, lane = tid & 31;

    unsigned mygen = *((volatile unsigned*)&g_gen2[g]);

    if (tid == 0) {
        asm volatile("mbarrier.init.shared.b64 [%0], %1;" :: "r"(mbar), "r"(1u) : "memory");
    }

    // --- stage W tile: 32 rows x 64 chunks(16B), fp32 -> fp16 hi/lo, chunk^=(row&7) ---
    #pragma unroll
    for (int i = 0; i < 8; ++i) {
        int gg = tid + i * 256;           // 2048 chunks
        int r = gg >> 6, k16 = gg & 63;
        int j = (r & 3) * 512 + c0 + (r >> 2);
        const float* src = Whh + (size_t)j * 512 + k16 * 8;
        float4 f0 = *(const float4*)(src);
        float4 f1 = *(const float4*)(src + 4);
        uint4 vh, vl;
        vh.x = split_pair_h(f0.x, f0.y, vl.x);
        vh.y = split_pair_h(f0.z, f0.w, vl.y);
        vh.z = split_pair_h(f1.x, f1.y, vl.z);
        vh.w = split_pair_h(f1.z, f1.w, vl.w);
        uint32_t off = (uint32_t)((r << 10) + (((k16 ^ (r & 7))) << 4));
        sts128(wHI + off, vh);
        sts128(wLO + off, vl);
    }

    // --- zero this block's chunk (ci) of both images of its group ---
    if (tid < 32) {
        int b = tid >> 1, img = tid & 1;
        uint32_t off = (uint32_t)((g * 2 + img) * 16384 + (b << 10) + (((ci ^ (b & 7))) << 4));
        *(uint4*)((char*)g_h2 + off) = make_uint4(0, 0, 0, 0);
    }
    __syncthreads();

    // GEMM thread mapping: 2m x 2n x 2k
    const int wm = wid & 1, wn = (wid >> 1) & 1, wk = wid >> 2;
    const int lrow = lane & 15, lk = lane >> 4;
    const uint32_t arowoff = (uint32_t)(((wm * 16 + lrow) << 10));
    const int ax7 = lrow & 7;

    // --- hoist W-hi fragments (this warp's k-half) into registers ---
    uint32_t AH[16][4];
    #pragma unroll
    for (int ks = 0; ks < 16; ++ks) {
        int ch = (wk * 16 + ks) * 2 + lk;
        uint32_t aoff = (uint32_t)(((ch ^ ax7)) << 4);
        ldmatrix4(AH[ks][0], AH[ks][1], AH[ks][2], AH[ks][3], wHI + arowoff + aoff);
    }

    // --- prologue: prefetch xg(0) + per-group initial barrier ---
    if (tid == 0) {
        asm volatile("mbarrier.arrive.expect_tx.shared.b64 _, [%0], %1;"
                     :: "r"(mbar), "r"(2048u) : "memory");
        asm volatile("cp.async.bulk.shared::cluster.global.mbarrier::complete_tx::bytes "
                     "[%0], [%1], %2, [%3];"
                     :: "r"(xgs_a), "l"((const char*)(xg + (size_t)bx * 512)), "r"(2048u), "r"(mbar) : "memory");
        __threadfence();
        unsigned a = atomicAdd(&g_barc[g], 1u);
        if (a == GRP - 1u) { g_barc[g] = 0u; st_release(&g_gen2[g], mygen + 1u); }
        else { while (ld_acquire(&g_gen2[g]) == mygen) {} }
    }
    mygen++;
    __syncthreads();
    MBAR_WAIT(mbar, 0u);

    // B-frag addressing (16 batch rows)
    const int brow = wn * 8 + (lane & 7);
    const uint32_t browoff = (uint32_t)(brow << 10);
    const int bx7 = brow & 7;
    const int bcs = (lane >> 3) & 1;

    // activation mapping: cl = tid>>4 (0..7), b_local = tid&15  (tid < 128)
    const int cl = tid >> 4;
    const int bb = tid & 15;
    float cst = 0.f;

    const char* hsrc = (const char*)g_h2 + g * 32768;

    for (int t = 0; t < T_; ++t) {
        // 1. bulk copies: h hi+lo (32KB) + xg(t+1) (2KB)
        if (tid == 0) {
            unsigned txb = 32768u + ((t + 1 < T_) ? 2048u : 0u);
            asm volatile("mbarrier.arrive.expect_tx.shared.b64 _, [%0], %1;"
                         :: "r"(mbar), "r"(txb) : "memory");
            asm volatile("cp.async.bulk.shared::cluster.global.mbarrier::complete_tx::bytes "
                         "[%0], [%1], %2, [%3];"
                         :: "r"(bHI), "l"(hsrc), "r"(32768u), "r"(mbar) : "memory");
            if (t + 1 < T_) {
                const char* xsrc = (const char*)(xg + (((size_t)(t + 1) * NBLK + bx) * 512));
                asm volatile("cp.async.bulk.shared::cluster.global.mbarrier::complete_tx::bytes "
                             "[%0], [%1], %2, [%3];"
                             :: "r"(xgs_a + (((t + 1) & 1) ? 2048u : 0u)), "l"(xsrc), "r"(2048u), "r"(mbar) : "memory");
            }
        }
        MBAR_WAIT(mbar, (uint32_t)((t + 1) & 1));

        // 2. GEMM: 16 k-steps (this warp's half), 3 accumulator chains
        float acc_a[4] = {0.f, 0.f, 0.f, 0.f};
        float acc_b[4] = {0.f, 0.f, 0.f, 0.f};
        float acc_c[4] = {0.f, 0.f, 0.f, 0.f};
        #pragma unroll
        for (int ks = 0; ks < 16; ++ks) {
            int chA = (wk * 16 + ks) * 2 + lk;
            int chB = (wk * 16 + ks) * 2 + bcs;
            uint32_t aoff = (uint32_t)(((chA ^ ax7)) << 4);
            uint32_t boff = (uint32_t)(((chB ^ bx7)) << 4);
            uint32_t al0, al1, al2, al3;
            uint32_t bh0, bh1, bl0, bl1;
            ldmatrix4(al0, al1, al2, al3, wLO + arowoff + aoff);
            ldmatrix2(bh0, bh1, bHI + browoff + boff);
            ldmatrix2(bl0, bl1, (bHI + 16384u) + browoff + boff);
            mma16816h(acc_a, AH[ks], bh0, bh1);
            mma16816h(acc_b, AH[ks], bl0, bl1);
            uint32_t alr[4] = {al0, al1, al2, al3};
            mma16816h(acc_c, alr, bh0, bh1);
        }

        // 3. combine + store per-k-half gates to gsm[wk]
        {
            int r0 = wm * 16 + (lane >> 2);
            int cb = wn * 8 + (lane & 3) * 2;
            float* gk = gsm + wk * (32 * 18);
            float s0 = acc_a[0] + acc_b[0] + acc_c[0];
            float s1 = acc_a[1] + acc_b[1] + acc_c[1];
            float s2 = acc_a[2] + acc_b[2] + acc_c[2];
            float s3 = acc_a[3] + acc_b[3] + acc_c[3];
            *(float2*)&gk[r0 * 18 + cb]       = make_float2(s0, s1);
            *(float2*)&gk[(r0 + 8) * 18 + cb] = make_float2(s2, s3);
        }
        __syncthreads();

        // 4. activation: thread (cl, bb); sum k-halves; c-state in reg
        if (tid < 128) {
            const float* xb2 = xgs + ((t & 1) ? 512 : 0) + bb * 32;
            int r = cl * 4;
            float gi = gsm[(r + 0) * 18 + bb] + gsm[576 + (r + 0) * 18 + bb] + xb2[cl];
            float gf = gsm[(r + 1) * 18 + bb] + gsm[576 + (r + 1) * 18 + bb] + xb2[8 + cl];
            float gg = gsm[(r + 2) * 18 + bb] + gsm[576 + (r + 2) * 18 + bb] + xb2[16 + cl];
            float go = gsm[(r + 3) * 18 + bb] + gsm[576 + (r + 3) * 18 + bb] + xb2[24 + cl];
            float iv = sigmoidf(gi);
            float fv = sigmoidf(gf);
            float gv = tanh_fast(gg);
            float ov = sigmoidf(go);
            cst = fv * cst + iv * gv;
            float hv = ov * tanh_fast(cst);
            __half hh = __float2half_rn(hv);
            hsmh[bb * 8 + cl] = hh;
            hsml[bb * 8 + cl] = __float2half_rn(hv - __half2float(hh));
            Y[((size_t)(g * 16 + bb) * T_ + t) * H_ + c0 + cl] = hv;
        }
        __syncthreads();

        // 5. publish h chunk (ci) of both group images
        if (tid < 32) {
            int b = tid >> 1, img = tid & 1;
            const __half* s = img ? hsml : hsmh;
            uint4 v = *(const uint4*)(s + b * 8);
            uint32_t off = (uint32_t)((g * 2 + img) * 16384 + (b << 10) + (((ci ^ (b & 7))) << 4));
            *(uint4*)((char*)g_h2 + off) = v;
        }

        // 6. per-group grid barrier
        __syncthreads();
        if (tid == 0) {
            __threadfence();
            unsigned a = atomicAdd(&g_barc[g], 1u);
            if (a == GRP - 1u) { g_barc[g] = 0u; st_release(&g_gen2[g], mygen + 1u); }
            else { while (ld_acquire(&g_gen2[g]) == mygen) {} }
        }
        mygen++;
        __syncthreads();
    }
}

// ---------------------------------------------------------------------------
// mean over T + head GEMV
// ---------------------------------------------------------------------------
__global__ void pool_head_kernel(const float* __restrict__ head_w,
                                 const float* __restrict__ head_b,
                                 float* __restrict__ out) {
    int b = blockIdx.x;
    int h = threadIdx.x;
    __shared__ float feat[H_];
    const float* Yp = g_bufB + (size_t)b * T_ * H_;
    float s = 0.f;
    for (int t = 0; t < T_; ++t) s += Yp[t * H_ + h];
    feat[h] = s * (1.0f / (float)T_);
    __syncthreads();
    for (int cc = threadIdx.x; cc < NCLS; cc += blockDim.x) {
        float a = head_b[cc];
        const float* wr = head_w + cc * H_;
        for (int k = 0; k < H_; ++k) a += feat[k] * wr[k];
        out[b * NCLS + cc] = a;
    }
}

// ---------------------------------------------------------------------------
extern "C" void kernel_launch(void* const* d_in, const int* in_sizes, int n_in,
                              void* d_out, int out_size) {
    const float* x     = (const float*)d_in[0];
    const float* convw = (const float*)d_in[1];
    const float* gamma = (const float*)d_in[2];
    const float* beta  = (const float*)d_in[3];

    bool head_first = (in_sizes[4] == NCLS * H_);
    int o = head_first ? 6 : 4;
    const float* headw = (const float*)d_in[head_first ? 4 : 13];
    const float* headb = (const float*)d_in[head_first ? 5 : 14];
    const float* wih[3] = { (const float*)d_in[o + 0], (const float*)d_in[o + 3], (const float*)d_in[o + 6] };
    const float* whh[3] = { (const float*)d_in[o + 1], (const float*)d_in[o + 4], (const float*)d_in[o + 7] };
    const float* bb[3]  = { (const float*)d_in[o + 2], (const float*)d_in[o + 5], (const float*)d_in[o + 8] };

    static int smem_set = 0;
    if (!smem_set) {
        cudaFuncSetAttribute(lstm_kernel, cudaFuncAttributeMaxDynamicSharedMemorySize, SMEM_REQ);
        cudaFuncSetAttribute(xg_hmma_kernel, cudaFuncAttributeMaxDynamicSharedMemorySize, XG_SMEM_REQ);
        smem_set = 1;
    }

    void* xgsym = nullptr;   cudaGetSymbolAddress(&xgsym, g_xg);
    void* bufAsym = nullptr; cudaGetSymbolAddress(&bufAsym, g_bufA);
    void* bufBsym = nullptr; cudaGetSymbolAddress(&bufBsym, g_bufB);

    conv_kernel<<<B_ * NF, 128>>>(x, convw);
    gn_kernel<<<B_ * GN_G, 256>>>(gamma, beta);

    for (int layer = 1; layer <= 3; ++layer) {
        int din = (layer == 1) ? NF : H_;
        dim3 gg(G4H / 128, (B_ * T_) / 128);
        xg_hmma_kernel<<<gg, 256, XG_SMEM_REQ>>>(layer, wih[layer - 1], bb[layer - 1], din);
        float* yptr = (layer == 2) ? (float*)bufAsym : (float*)bufBsym;
        lstm_kernel<<<NBLK, THR, SMEM_REQ>>>(whh[layer - 1], (const float*)xgsym, yptr);
    }

    pool_head_kernel<<<B_, H_>>>(headw, headb, (float*)d_out);
}

// round 11
// speedup vs baseline: 1.6407x; 1.0372x over previous
#include <cuda_runtime.h>
#include <cuda_bf16.h>
#include <cuda_fp16.h>
#include <cstdint>

// ---------------------------------------------------------------------------
// MetaCNNLSTM: conv1d(64->256,k9,same) + GN(8)+ReLU -> 3x LSTM(512) -> mean -> head(50)
// B=32, T=512.
// LSTM: batch split into 4 independent groups of 8; each group = 32 persistent
// blocks (16 cells each) with its own atomic+gen barrier (R6/R9/R10-proven).
// Compensated fp16 HMMA (3 passes), W-hi fragments in registers, warps split
// 4m x 2k-halves (N=8 whole), bulk-copied operands, double-buffered xg prefetch.
// ---------------------------------------------------------------------------

#define B_      32
#define CIN     64
#define T_      512
#define NF      256
#define GN_G    8
#define KW      9
#define H_      512
#define G4H     2048
#define NCLS    50

#define NBLK    128            // 4 groups x 32 blocks
#define GRP     32
#define THR     256

// lstm dynamic smem layout (byte offsets from 1024-aligned base)
#define SM_WHI   0          // W hi: 64 rows x 64 chunks(16B) fp16, chunk^=(row&7)  65536
#define SM_WLO   65536      // W lo                                                 65536
#define SM_BHI   131072     // h hi: 8 rows x 64 chunks                              8192
#define SM_BLO   139264     // h lo (contiguous: one bulk copy)                      8192
#define SM_GSM   147456     // gates 2(k-half) x [64][10] fp32                       5120
#define SM_XGS   152576     // xg staging 2 x [8][64] fp32                           4096
#define SM_HSMH  156672     // h hi staging [8][16] fp16                              256
#define SM_HSML  156928     // h lo staging                                           256
#define SM_MBAR  157184     // mbarrier (8B)
#define SM_TOTAL 157192
#define SMEM_REQ (SM_TOTAL + 1024)

// xg HMMA kernel smem layout
#define XGS_AHI  0          // A hi: 128 rows x 16 chunks(16B), chunk^=(row&7)  32768
#define XGS_ALO  32768
#define XGS_BHI  65536
#define XGS_BLO  98304
#define XG_SMEM_TOTAL 131072
#define XG_SMEM_REQ (XG_SMEM_TOTAL + 1024)

// ---- global scratch ----
__device__ float g_conv[B_ * NF * T_];
__device__ float g_bufA[B_ * T_ * H_];
__device__ float g_bufB[B_ * T_ * H_];
// [t][blk(128)][b_local(8)][gate*16+cl]  -- 2KB per (t, blk)
__device__ __align__(4096) float g_xg[T_ * NBLK * 8 * 64];
// h: [group(4)][img(2)][b_local(8) rows of 1024B, chunk k16^(b&7)] = 4 x 16KB
__device__ __align__(1024) __half g_h2[4 * 2 * 8 * H_];
// barrier counters/gens padded 128B apart (4 groups, no LTS address collision)
__device__ unsigned g_barc[4 * 32];
__device__ unsigned g_gen2[4 * 32];

// ---------------------------------------------------------------------------
// helpers
// ---------------------------------------------------------------------------
__device__ __forceinline__ float sigmoidf(float x) { return 1.0f / (1.0f + __expf(-x)); }
__device__ __forceinline__ float tanh_fast(float x) { return 1.0f - 2.0f / (1.0f + __expf(2.0f * x)); }

__device__ __forceinline__ unsigned ld_acquire(unsigned* p) {
    unsigned v;
    asm volatile("ld.acquire.gpu.global.u32 %0, [%1];" : "=r"(v) : "l"(p) : "memory");
    return v;
}
__device__ __forceinline__ void st_release(unsigned* p, unsigned v) {
    asm volatile("st.release.gpu.global.u32 [%0], %1;" :: "l"(p), "r"(v) : "memory");
}
__device__ __forceinline__ uint32_t smem_u32(const void* p) {
    uint32_t a;
    asm("{ .reg .u64 t; cvta.to.shared.u64 t, %1; cvt.u32.u64 %0, t; }" : "=r"(a) : "l"(p));
    return a;
}
__device__ __forceinline__ uint32_t split_pair_h(float a, float b, uint32_t& lo_out) {
    __half ha = __float2half_rn(a), hb = __float2half_rn(b);
    float la = a - __half2float(ha);
    float lb = b - __half2float(hb);
    __half2 lo2 = __halves2half2(__float2half_rn(la), __float2half_rn(lb));
    __half2 hi2 = __halves2half2(ha, hb);
    lo_out = *reinterpret_cast<uint32_t*>(&lo2);
    return *reinterpret_cast<uint32_t*>(&hi2);
}
__device__ __forceinline__ void sts128(uint32_t addr, uint4 v) {
    asm volatile("st.shared.v4.b32 [%0], {%1,%2,%3,%4};"
                 :: "r"(addr), "r"(v.x), "r"(v.y), "r"(v.z), "r"(v.w) : "memory");
}
__device__ __forceinline__ void ldmatrix4(uint32_t& r0, uint32_t& r1, uint32_t& r2, uint32_t& r3, uint32_t addr) {
    asm volatile("ldmatrix.sync.aligned.m8n8.x4.shared.b16 {%0,%1,%2,%3}, [%4];"
                 : "=r"(r0), "=r"(r1), "=r"(r2), "=r"(r3) : "r"(addr));
}
__device__ __forceinline__ void ldmatrix2(uint32_t& r0, uint32_t& r1, uint32_t addr) {
    asm volatile("ldmatrix.sync.aligned.m8n8.x2.shared.b16 {%0,%1}, [%2];"
                 : "=r"(r0), "=r"(r1) : "r"(addr));
}
__device__ __forceinline__ void mma16816h(float* c, const uint32_t* a, uint32_t b0, uint32_t b1) {
    asm volatile("mma.sync.aligned.m16n8k16.row.col.f32.f16.f16.f32 "
                 "{%0,%1,%2,%3}, {%4,%5,%6,%7}, {%8,%9}, {%0,%1,%2,%3};"
                 : "+f"(c[0]), "+f"(c[1]), "+f"(c[2]), "+f"(c[3])
                 : "r"(a[0]), "r"(a[1]), "r"(a[2]), "r"(a[3]), "r"(b0), "r"(b1));
}

#define MBAR_WAIT(mbar, ph) do {                                                   \
    uint32_t _done;                                                                \
    asm volatile("{\n\t.reg .pred p;\n\t"                                          \
        "mbarrier.try_wait.parity.acquire.cta.shared::cta.b64 p, [%1], %2;\n\t"    \
        "selp.b32 %0, 1, 0, p;\n\t}"                                               \
        : "=r"(_done) : "r"(mbar), "r"(ph) : "memory");                            \
    if (!_done) {                                                                  \
        asm volatile("{\n\t.reg .pred P1;\n\t"                                     \
            "WL_%=:\n\t"                                                           \
            "mbarrier.try_wait.parity.acquire.cta.shared::cta.b64 P1, [%0], %1, 0x989680;\n\t" \
            "@P1 bra.uni WD_%=;\n\t"                                               \
            "bra.uni WL_%=;\n\t"                                                   \
            "WD_%=:\n\t}"                                                          \
            :: "r"(mbar), "r"(ph) : "memory");                                     \
    }                                                                              \
} while (0)

// ---------------------------------------------------------------------------
// conv1d
// ---------------------------------------------------------------------------
__global__ void conv_kernel(const float* __restrict__ x, const float* __restrict__ w) {
    int bf = blockIdx.x;
    int b = bf >> 8, f = bf & 255;
    __shared__ float wsh[CIN * KW];
    for (int e = threadIdx.x; e < CIN * KW; e += blockDim.x)
        wsh[e] = w[f * CIN * KW + e];
    __syncthreads();
    const float* xb = x + b * CIN * T_;
    #pragma unroll
    for (int tt = 0; tt < 4; ++tt) {
        int t = tt * 128 + threadIdx.x;
        float acc = 0.f;
        for (int c = 0; c < CIN; ++c) {
            const float* xr = xb + c * T_;
            const float* wr = wsh + c * KW;
            #pragma unroll
            for (int k = 0; k < KW; ++k) {
                int ti = t + k - 4;
                if (ti >= 0 && ti < T_) acc += xr[ti] * wr[k];
            }
        }
        g_conv[(b * NF + f) * T_ + t] = acc;
    }
}

// ---------------------------------------------------------------------------
// fused GroupNorm (stats + apply + ReLU + transpose -> g_bufA)
// ---------------------------------------------------------------------------
__global__ void gn_kernel(const float* __restrict__ gamma, const float* __restrict__ beta) {
    int bg = blockIdx.x;
    int b = bg >> 3, g = bg & 7;
    const float* base = g_conv + (b * NF + g * 32) * T_;
    float s = 0.f, ss = 0.f;
    for (int e = threadIdx.x; e < 32 * T_; e += blockDim.x) {
        float v = base[e];
        s += v; ss += v * v;
    }
    __shared__ float sh_s[256], sh_q[256];
    sh_s[threadIdx.x] = s; sh_q[threadIdx.x] = ss;
    __syncthreads();
    for (int st = 128; st > 0; st >>= 1) {
        if (threadIdx.x < st) {
            sh_s[threadIdx.x] += sh_s[threadIdx.x + st];
            sh_q[threadIdx.x] += sh_q[threadIdx.x + st];
        }
        __syncthreads();
    }
    __shared__ float sh_mu, sh_rs;
    if (threadIdx.x == 0) {
        float n = 32.0f * (float)T_;
        float mu = sh_s[0] / n;
        float var = sh_q[0] / n - mu * mu;
        sh_mu = mu;
        sh_rs = rsqrtf(var + 1e-5f);
    }
    __syncthreads();
    float mu = sh_mu, rs = sh_rs;
    for (int e = threadIdx.x; e < 32 * T_; e += blockDim.x) {
        int cl = e >> 9, t = e & 511;
        int f = g * 32 + cl;
        float v = (base[e] - mu) * rs * gamma[f] + beta[f];
        v = fmaxf(v, 0.f);
        g_bufA[(b * T_ + t) * NF + f] = v;
    }
}

// ---------------------------------------------------------------------------
// xg projection GEMM on HMMA (compensated fp16, 3 passes).
// output: g_xg[((t*128 + blk)*8 + b_local)*64 + gate*16 + cl]
//   blk = (b>>3)*32 + (cell>>4), b_local = b&7, cl = cell&15
// ---------------------------------------------------------------------------
__global__ __launch_bounds__(256) void xg_hmma_kernel(int layer,
                                                      const float* __restrict__ Wih,
                                                      const float* __restrict__ bias,
                                                      int Din) {
    const float* X = (layer == 2) ? g_bufB : g_bufA;
    extern __shared__ char smraw[];
    uint32_t rawa = smem_u32(smraw);
    uint32_t base = (rawa + 1023u) & ~1023u;
    uint32_t aHI = base + XGS_AHI;
    uint32_t aLO = base + XGS_ALO;
    uint32_t bHI = base + XGS_BHI;
    uint32_t bLO = base + XGS_BLO;

    const int tid = threadIdx.x;
    const int wid = tid >> 5, lane = tid & 31;
    const int n0 = blockIdx.x * 128, m0 = blockIdx.y * 128;

    const int wm = wid & 1, wn = wid >> 1;
    const int lrow = lane & 15, lk = lane >> 4;
    const int bcs = (lane >> 3) & 1;

    const int r = tid & 127, hf = tid >> 7;
    const int mg = m0 + r;
    const float* asrc0 = X + ((size_t)(mg & 31) * T_ + (mg >> 5)) * Din + hf * 64;
    const float* bsrc0 = Wih + (size_t)(n0 + r) * Din + hf * 64;
    const uint32_t stoff0 = (uint32_t)(r * 256);

    float acc[4][4][4];
    #pragma unroll
    for (int mi = 0; mi < 4; ++mi)
        #pragma unroll
        for (int ni = 0; ni < 4; ++ni)
            #pragma unroll
            for (int q = 0; q < 4; ++q) acc[mi][ni][q] = 0.f;

    const int nchunks = Din >> 7;
    for (int kc = 0; kc < nchunks; ++kc) {
        const float* asrc = asrc0 + kc * 128;
        const float* bsrc = bsrc0 + kc * 128;
        #pragma unroll
        for (int j = 0; j < 8; ++j) {
            int c = hf * 8 + j;
            uint32_t off = stoff0 + (uint32_t)(((c ^ (r & 7))) << 4);
            {
                float4 f0 = *(const float4*)(asrc + j * 8);
                float4 f1 = *(const float4*)(asrc + j * 8 + 4);
                uint4 vh, vl;
                vh.x = split_pair_h(f0.x, f0.y, vl.x);
                vh.y = split_pair_h(f0.z, f0.w, vl.y);
                vh.z = split_pair_h(f1.x, f1.y, vl.z);
                vh.w = split_pair_h(f1.z, f1.w, vl.w);
                sts128(aHI + off, vh);
                sts128(aLO + off, vl);
            }
            {
                float4 f0 = *(const float4*)(bsrc + j * 8);
                float4 f1 = *(const float4*)(bsrc + j * 8 + 4);
                uint4 vh, vl;
                vh.x = split_pair_h(f0.x, f0.y, vl.x);
                vh.y = split_pair_h(f0.z, f0.w, vl.y);
                vh.z = split_pair_h(f1.x, f1.y, vl.z);
                vh.w = split_pair_h(f1.z, f1.w, vl.w);
                sts128(bHI + off, vh);
                sts128(bLO + off, vl);
            }
        }
        __syncthreads();

        #pragma unroll
        for (int s = 0; s < 8; ++s) {
            uint32_t ahf[4][4], alf[4][4], bhf[4][2], blf[4][2];
            #pragma unroll
            for (int mi = 0; mi < 4; ++mi) {
                int rowA = wm * 64 + mi * 16 + lrow;
                uint32_t aoff = (uint32_t)(rowA * 256 + (((2 * s + lk) ^ (rowA & 7)) << 4));
                ldmatrix4(ahf[mi][0], ahf[mi][1], ahf[mi][2], ahf[mi][3], aHI + aoff);
                ldmatrix4(alf[mi][0], alf[mi][1], alf[mi][2], alf[mi][3], aLO + aoff);
            }
            #pragma unroll
            for (int ni = 0; ni < 4; ++ni) {
                int rowB = wn * 32 + ni * 8 + (lane & 7);
                uint32_t boff = (uint32_t)(rowB * 256 + (((2 * s + bcs) ^ (rowB & 7)) << 4));
                ldmatrix2(bhf[ni][0], bhf[ni][1], bHI + boff);
                ldmatrix2(blf[ni][0], blf[ni][1], bLO + boff);
            }
            #pragma unroll
            for (int mi = 0; mi < 4; ++mi)
                #pragma unroll
                for (int ni = 0; ni < 4; ++ni) {
                    mma16816h(acc[mi][ni], ahf[mi], bhf[ni][0], bhf[ni][1]);
                    mma16816h(acc[mi][ni], ahf[mi], blf[ni][0], blf[ni][1]);
                    mma16816h(acc[mi][ni], alf[mi], bhf[ni][0], bhf[ni][1]);
                }
        }
        __syncthreads();
    }

    // epilogue: bias + scatter (block-contiguous group layout)
    #pragma unroll
    for (int mi = 0; mi < 4; ++mi) {
        #pragma unroll
        for (int ni = 0; ni < 4; ++ni) {
            int cb = n0 + wn * 32 + ni * 8 + (lane & 3) * 2;
            int gate = cb >> 9, cell = cb & 511;
            int cblk = cell >> 4, cl = cell & 15;
            float bz0 = bias[cb], bz1 = bias[cb + 1];
            #pragma unroll
            for (int hrow = 0; hrow < 2; ++hrow) {
                int row = m0 + wm * 64 + mi * 16 + (lane >> 2) + hrow * 8;
                int t = row >> 5, b = row & 31;
                int blk = (b >> 3) * 32 + cblk;
                float2 v = make_float2(acc[mi][ni][hrow * 2 + 0] + bz0,
                                       acc[mi][ni][hrow * 2 + 1] + bz1);
                *(float2*)&g_xg[(((size_t)t * NBLK + blk) * 8 + (b & 7)) * 64 + gate * 16 + cl] = v;
            }
        }
    }
}

// ---------------------------------------------------------------------------
// persistent HMMA LSTM: 4 groups x 32 blocks. Block bx: group g=bx>>5 (batches
// g*8..+8), cells (bx&31)*16..+16. A row r <-> (gate=r&3, cell=c0+(r>>2)).
// 8 warps = 4(m16) x 2(k-half); N=8 whole. k-halves reduced in smem.
// ---------------------------------------------------------------------------
__global__ __launch_bounds__(THR, 1) void lstm_kernel(const float* __restrict__ Whh,
                                                      const float* __restrict__ xg,
                                                      float* __restrict__ Y) {
    extern __shared__ char smraw[];
    uint32_t rawa = smem_u32(smraw);
    uint32_t base = (rawa + 1023u) & ~1023u;
    char* sbase = smraw + (base - rawa);
    uint32_t wHI  = base + SM_WHI;
    uint32_t wLO  = base + SM_WLO;
    uint32_t bHI  = base + SM_BHI;
    float*   gsm  = (float*)(sbase + SM_GSM);
    float*   xgs  = (float*)(sbase + SM_XGS);
    __half*  hsmh = (__half*)(sbase + SM_HSMH);
    __half*  hsml = (__half*)(sbase + SM_HSML);
    uint32_t mbar = base + SM_MBAR;
    uint32_t xgs_a = base + SM_XGS;

    const int tid = threadIdx.x;
    const int bx = blockIdx.x;
    const int g  = bx >> 5;            // batch group (0..3)
    const int ci = bx & 31;            // cell-block index (0..31)
    const int c0 = ci * 16;
    const int wid = tid >> 5, lane = tid & 31;

    unsigned* barc = &g_barc[g * 32];
    unsigned* genp = &g_gen2[g * 32];
    unsigned mygen = *((volatile unsigned*)genp);

    if (tid == 0) {
        asm volatile("mbarrier.init.shared.b64 [%0], %1;" :: "r"(mbar), "r"(1u) : "memory");
    }

    // --- stage W tile: 64 rows x 64 chunks(16B), fp32 -> fp16 hi/lo, chunk^=(row&7) ---
    #pragma unroll
    for (int i = 0; i < 16; ++i) {
        int gg = tid + i * 256;           // 4096 chunks
        int r = gg >> 6, k16 = gg & 63;
        int j = (r & 3) * 512 + c0 + (r >> 2);
        const float* src = Whh + (size_t)j * 512 + k16 * 8;
        float4 f0 = *(const float4*)(src);
        float4 f1 = *(const float4*)(src + 4);
        uint4 vh, vl;
        vh.x = split_pair_h(f0.x, f0.y, vl.x);
        vh.y = split_pair_h(f0.z, f0.w, vl.y);
        vh.z = split_pair_h(f1.x, f1.y, vl.z);
        vh.w = split_pair_h(f1.z, f1.w, vl.w);
        uint32_t off = (uint32_t)((r << 10) + (((k16 ^ (r & 7))) << 4));
        sts128(wHI + off, vh);
        sts128(wLO + off, vl);
    }

    // --- zero this block's chunks (2ci, 2ci+1) of both images of its group ---
    if (tid < 32) {
        int q = tid & 1, b = (tid >> 1) & 7, img = tid >> 4;
        uint32_t off = (uint32_t)(((g * 2 + img) * 8 + b) * 1024 + (((2 * ci + q) ^ (b & 7)) << 4));
        *(uint4*)((char*)g_h2 + off) = make_uint4(0, 0, 0, 0);
    }
    __syncthreads();

    // GEMM thread mapping: 4m x 2k
    const int wm = wid & 3, wk = wid >> 2;
    const int lrow = lane & 15, lk = lane >> 4;
    const uint32_t arowoff = (uint32_t)(((wm * 16 + lrow) << 10));
    const int ax7 = lrow & 7;

    // --- hoist W-hi fragments (this warp's k-half) into registers ---
    uint32_t AH[16][4];
    #pragma unroll
    for (int ks = 0; ks < 16; ++ks) {
        int ch = (wk * 16 + ks) * 2 + lk;
        uint32_t aoff = (uint32_t)(((ch ^ ax7)) << 4);
        ldmatrix4(AH[ks][0], AH[ks][1], AH[ks][2], AH[ks][3], wHI + arowoff + aoff);
    }

    // --- prologue: prefetch xg(0) + per-group initial barrier ---
    if (tid == 0) {
        asm volatile("mbarrier.arrive.expect_tx.shared.b64 _, [%0], %1;"
                     :: "r"(mbar), "r"(2048u) : "memory");
        asm volatile("cp.async.bulk.shared::cluster.global.mbarrier::complete_tx::bytes "
                     "[%0], [%1], %2, [%3];"
                     :: "r"(xgs_a), "l"((const char*)(xg + (size_t)bx * 512)), "r"(2048u), "r"(mbar) : "memory");
        __threadfence();
        unsigned a = atomicAdd(barc, 1u);
        if (a == GRP - 1u) { *barc = 0u; st_release(genp, mygen + 1u); }
        else { while (ld_acquire(genp) == mygen) {} }
    }
    mygen++;
    __syncthreads();
    MBAR_WAIT(mbar, 0u);

    // B-frag addressing (8 batch rows)
    const int brow = lane & 7;
    const uint32_t browoff = (uint32_t)(brow << 10);
    const int bx7 = brow;
    const int bcs = (lane >> 3) & 1;

    // activation mapping: cl = tid>>3 (0..15), b_local = tid&7  (tid < 128)
    const int cl = tid >> 3;
    const int bb = tid & 7;
    float cst = 0.f;

    const char* hsrc = (const char*)g_h2 + g * 16384;

    for (int t = 0; t < T_; ++t) {
        // 1. bulk copies: h hi+lo (16KB) + xg(t+1) (2KB)
        if (tid == 0) {
            unsigned txb = 16384u + ((t + 1 < T_) ? 2048u : 0u);
            asm volatile("mbarrier.arrive.expect_tx.shared.b64 _, [%0], %1;"
                         :: "r"(mbar), "r"(txb) : "memory");
            asm volatile("cp.async.bulk.shared::cluster.global.mbarrier::complete_tx::bytes "
                         "[%0], [%1], %2, [%3];"
                         :: "r"(bHI), "l"(hsrc), "r"(16384u), "r"(mbar) : "memory");
            if (t + 1 < T_) {
                const char* xsrc = (const char*)(xg + (((size_t)(t + 1) * NBLK + bx) * 512));
                asm volatile("cp.async.bulk.shared::cluster.global.mbarrier::complete_tx::bytes "
                             "[%0], [%1], %2, [%3];"
                             :: "r"(xgs_a + (((t + 1) & 1) ? 2048u : 0u)), "l"(xsrc), "r"(2048u), "r"(mbar) : "memory");
            }
        }
        MBAR_WAIT(mbar, (uint32_t)((t + 1) & 1));

        // 2. GEMM: 16 k-steps (this warp's half), 3 accumulator chains
        float acc_a[4] = {0.f, 0.f, 0.f, 0.f};
        float acc_b[4] = {0.f, 0.f, 0.f, 0.f};
        float acc_c[4] = {0.f, 0.f, 0.f, 0.f};
        #pragma unroll
        for (int ks = 0; ks < 16; ++ks) {
            int chA = (wk * 16 + ks) * 2 + lk;
            int chB = (wk * 16 + ks) * 2 + bcs;
            uint32_t aoff = (uint32_t)(((chA ^ ax7)) << 4);
            uint32_t boff = (uint32_t)(((chB ^ bx7)) << 4);
            uint32_t al0, al1, al2, al3;
            uint32_t bh0, bh1, bl0, bl1;
            ldmatrix4(al0, al1, al2, al3, wLO + arowoff + aoff);
            ldmatrix2(bh0, bh1, bHI + browoff + boff);
            ldmatrix2(bl0, bl1, (bHI + 8192u) + browoff + boff);
            mma16816h(acc_a, AH[ks], bh0, bh1);
            mma16816h(acc_b, AH[ks], bl0, bl1);
            uint32_t alr[4] = {al0, al1, al2, al3};
            mma16816h(acc_c, alr, bh0, bh1);
        }

        // 3. combine + store per-k-half gates to gsm[wk] ([64][10])
        {
            int r0 = wm * 16 + (lane >> 2);
            int cb = (lane & 3) * 2;
            float* gk = gsm + wk * 640;
            float s0 = acc_a[0] + acc_b[0] + acc_c[0];
            float s1 = acc_a[1] + acc_b[1] + acc_c[1];
            float s2 = acc_a[2] + acc_b[2] + acc_c[2];
            float s3 = acc_a[3] + acc_b[3] + acc_c[3];
            *(float2*)&gk[r0 * 10 + cb]       = make_float2(s0, s1);
            *(float2*)&gk[(r0 + 8) * 10 + cb] = make_float2(s2, s3);
        }
        __syncthreads();

        // 4. activation: thread (cl, bb); sum k-halves; c-state in reg
        if (tid < 128) {
            const float* xb2 = xgs + ((t & 1) ? 512 : 0) + bb * 64;
            int r = cl * 4;
            float gi = gsm[(r + 0) * 10 + bb] + gsm[640 + (r + 0) * 10 + bb] + xb2[cl];
            float gf = gsm[(r + 1) * 10 + bb] + gsm[640 + (r + 1) * 10 + bb] + xb2[16 + cl];
            float gg = gsm[(r + 2) * 10 + bb] + gsm[640 + (r + 2) * 10 + bb] + xb2[32 + cl];
            float go = gsm[(r + 3) * 10 + bb] + gsm[640 + (r + 3) * 10 + bb] + xb2[48 + cl];
            float iv = sigmoidf(gi);
            float fv = sigmoidf(gf);
            float gv = tanh_fast(gg);
            float ov = sigmoidf(go);
            cst = fv * cst + iv * gv;
            float hv = ov * tanh_fast(cst);
            __half hh = __float2half_rn(hv);
            hsmh[bb * 16 + cl] = hh;
            hsml[bb * 16 + cl] = __float2half_rn(hv - __half2float(hh));
            Y[((size_t)(g * 8 + bb) * T_ + t) * H_ + c0 + cl] = hv;
        }
        __syncthreads();

        // 5. publish h chunks (2ci, 2ci+1) of both group images
        if (tid < 32) {
            int q = tid & 1, b = (tid >> 1) & 7, img = tid >> 4;
            const __half* s = img ? hsml : hsmh;
            uint4 v = *(const uint4*)(s + b * 16 + q * 8);
            uint32_t off = (uint32_t)(((g * 2 + img) * 8 + b) * 1024 + (((2 * ci + q) ^ (b & 7)) << 4));
            *(uint4*)((char*)g_h2 + off) = v;
        }

        // 6. per-group grid barrier
        __syncthreads();
        if (tid == 0) {
            __threadfence();
            unsigned a = atomicAdd(barc, 1u);
            if (a == GRP - 1u) { *barc = 0u; st_release(genp, mygen + 1u); }
            else { while (ld_acquire(genp) == mygen) {} }
        }
        mygen++;
        __syncthreads();
    }
}

// ---------------------------------------------------------------------------
// mean over T + head GEMV
// ---------------------------------------------------------------------------
__global__ void pool_head_kernel(const float* __restrict__ head_w,
                                 const float* __restrict__ head_b,
                                 float* __restrict__ out) {
    int b = blockIdx.x;
    int h = threadIdx.x;
    __shared__ float feat[H_];
    const float* Yp = g_bufB + (size_t)b * T_ * H_;
    float s = 0.f;
    for (int t = 0; t < T_; ++t) s += Yp[t * H_ + h];
    feat[h] = s * (1.0f / (float)T_);
    __syncthreads();
    for (int cc = threadIdx.x; cc < NCLS; cc += blockDim.x) {
        float a = head_b[cc];
        const float* wr = head_w + cc * H_;
        for (int k = 0; k < H_; ++k) a += feat[k] * wr[k];
        out[b * NCLS + cc] = a;
    }
}

// ---------------------------------------------------------------------------
extern "C" void kernel_launch(void* const* d_in, const int* in_sizes, int n_in,
                              void* d_out, int out_size) {
    const float* x     = (const float*)d_in[0];
    const float* convw = (const float*)d_in[1];
    const float* gamma = (const float*)d_in[2];
    const float* beta  = (const float*)d_in[3];

    bool head_first = (in_sizes[4] == NCLS * H_);
    int o = head_first ? 6 : 4;
    const float* headw = (const float*)d_in[head_first ? 4 : 13];
    const float* headb = (const float*)d_in[head_first ? 5 : 14];
    const float* wih[3] = { (const float*)d_in[o + 0], (const float*)d_in[o + 3], (const float*)d_in[o + 6] };
    const float* whh[3] = { (const float*)d_in[o + 1], (const float*)d_in[o + 4], (const float*)d_in[o + 7] };
    const float* bb[3]  = { (const float*)d_in[o + 2], (const float*)d_in[o + 5], (const float*)d_in[o + 8] };

    static int smem_set = 0;
    if (!smem_set) {
        cudaFuncSetAttribute(lstm_kernel, cudaFuncAttributeMaxDynamicSharedMemorySize, SMEM_REQ);
        cudaFuncSetAttribute(xg_hmma_kernel, cudaFuncAttributeMaxDynamicSharedMemorySize, XG_SMEM_REQ);
        smem_set = 1;
    }

    void* xgsym = nullptr;   cudaGetSymbolAddress(&xgsym, g_xg);
    void* bufAsym = nullptr; cudaGetSymbolAddress(&bufAsym, g_bufA);
    void* bufBsym = nullptr; cudaGetSymbolAddress(&bufBsym, g_bufB);

    conv_kernel<<<B_ * NF, 128>>>(x, convw);
    gn_kernel<<<B_ * GN_G, 256>>>(gamma, beta);

    for (int layer = 1; layer <= 3; ++layer) {
        int din = (layer == 1) ? NF : H_;
        dim3 gg(G4H / 128, (B_ * T_) / 128);
        xg_hmma_kernel<<<gg, 256, XG_SMEM_REQ>>>(layer, wih[layer - 1], bb[layer - 1], din);
        float* yptr = (layer == 2) ? (float*)bufAsym : (float*)bufBsym;
        lstm_kernel<<<NBLK, THR, SMEM_REQ>>>(whh[layer - 1], (const float*)xgsym, yptr);
    }

    pool_head_kernel<<<B_, H_>>>(headw, headb, (float*)d_out);
}